// round 9
// baseline (speedup 1.0000x reference)
#include <cuda_runtime.h>
#include <cuda_bf16.h>
#include <math.h>
#include <stdint.h>

// ---------------- problem constants ----------------
#define NN   768
#define FF   64
#define VV   16
#define NB   8
#define HR   64
#define TT   2
#define ROS  32
#define ROV  16
#define PP   176
#define AVGI (1.0f/767.0f)

#define TILE   128
#define BLOCKE 704        // 22 warps: one warp per 8 p-columns

// double-buffered tile storage (floats)
#define BUF_F   23040     // per-buffer: H2 8192 + EST 8192 + EVT 6144 + RHT 512
#define F_H2    0
#define F_EST   8192
#define F_EVT   16384
#define F_RHT   22528
#define OFF_W2  (2*BUF_F)          // 46080  [64][176]
#define OFF_W1  (OFF_W2+11264)     // 57344  [8][64]
#define OFF_B1  (OFF_W1+512)       // 57856  [64]
#define SMEM_FLOATS (OFF_B1+64)    // 57920
#define SMEM_BYTES  (SMEM_FLOATS*4)   // 231680 <= 232448 OK

typedef unsigned long long u64;

__device__ __forceinline__ u64 pack2(float lo, float hi) {
    u64 r; asm("mov.b64 %0,{%1,%2};" : "=l"(r) : "f"(lo), "f"(hi)); return r;
}
__device__ __forceinline__ void unpack2(u64 v, float& lo, float& hi) {
    asm("mov.b64 {%0,%1},%2;" : "=f"(lo), "=f"(hi) : "l"(v));
}
__device__ __forceinline__ u64 fma2(u64 a, u64 b, u64 c) {
    u64 d; asm("fma.rn.f32x2 %0,%1,%2,%3;" : "=l"(d) : "l"(a), "l"(b), "l"(c)); return d;
}

// ---------------- device scratch ----------------
__device__ float g_hsT[FF*NN];      // transposed: [f][node]
__device__ float g_hvT[48*NN];
__device__ float g_aggs[NN*80];
__device__ float g_aggv[NN*288];
__device__ float g_com[3];

// ---------------- prep0: com + layer-0 transform (broadcast) ----------------
__global__ void prep0(const float* __restrict__ x,
                      const float* __restrict__ embed,
                      const float* __restrict__ wns0) {
    __shared__ float s0[24], s1[24], s2[24], sE[64];
    int i = threadIdx.x;           // 768 threads
    float v0 = x[i*3+0], v1 = x[i*3+1], v2 = x[i*3+2];
    #pragma unroll
    for (int o = 16; o > 0; o >>= 1) {
        v0 += __shfl_down_sync(0xffffffffu, v0, o);
        v1 += __shfl_down_sync(0xffffffffu, v1, o);
        v2 += __shfl_down_sync(0xffffffffu, v2, o);
    }
    if ((i & 31) == 0) { s0[i>>5]=v0; s1[i>>5]=v1; s2[i>>5]=v2; }
    if (i < 64) {
        float a = 0.f;
        #pragma unroll
        for (int k = 0; k < 64; k++) a = fmaf(embed[k], wns0[k*64 + i], a);
        sE[i] = a;
    }
    __syncthreads();
    if (i == 0) {
        float a0=0,a1=0,a2=0;
        for (int w = 0; w < 24; w++) { a0+=s0[w]; a1+=s1[w]; a2+=s2[w]; }
        g_com[0]=a0/768.f; g_com[1]=a1/768.f; g_com[2]=a2/768.f;
    }
    for (int j = i; j < 64*NN; j += 768) g_hsT[j] = sE[j / NN];
    for (int j = i; j < 48*NN; j += 768) g_hvT[j] = 0.f;
}

// ---------------- tile producer: staging + radial MLP ----------------
__device__ __forceinline__ void produce_tile(
    float* buf, const float* __restrict__ x,
    const float* sW1, const float* sB1,
    int t0, int rcv, float xr0, float xr1, float xr2, int tid, int has_v)
{
    float* sH2  = buf + F_H2;
    float* sEST = buf + F_EST;
    float* sEVT = buf + F_EVT;
    float* sRHT = buf + F_RHT;
    for (int i = tid; i < 64*TILE; i += BLOCKE) {
        int f = i >> 7, e = i & 127;
        sEST[i] = g_hsT[f*NN + t0 + e];
    }
    if (has_v) {
        for (int i = tid; i < 48*TILE; i += BLOCKE) {
            int f = i >> 7, e = i & 127;
            sEVT[i] = g_hvT[f*NN + t0 + e];
        }
    }
    if (tid < 512) {
        const int e  = tid & 127;
        const int g  = tid >> 7;        // 0..3, 16 h each
        const int s  = t0 + e;
        const float vx = xr0 - __ldg(&x[s*3+0]);
        const float vy = xr1 - __ldg(&x[s*3+1]);
        const float vz = xr2 - __ldg(&x[s*3+2]);
        const float rr = sqrtf(vx*vx + vy*vy + vz*vz);
        const bool self = (s == rcv);
        const float rinv = self ? 0.f : (1.f / rr);
        if (g == 0) {
            sRHT[0*128+e] = vx*rinv;
            sRHT[1*128+e] = vy*rinv;
            sRHT[2*128+e] = vz*rinv;
        }
        const float rg = self ? 1.f : rr;
        float sa, ca;
        __sincosf(0.31415926535f * rg, &sa, &ca);   // pi/RMAX
        const float coef = 0.4472135955f * rinv;    // sqrt(2/RMAX)/r
        u64 rbp[8];
        {
            float sp = 0.f, sc = sa;
            const float twoc = 2.f*ca;
            #pragma unroll
            for (int nb = 0; nb < 8; nb++) {
                float rb = sc * coef;
                rbp[nb] = pack2(rb, rb);
                float sn = fmaf(twoc, sc, -sp);
                sp = sc; sc = sn;
            }
        }
        const float u = 2.f * (1.f - rr*0.1f);
        const float env = (!self && u > 0.f) ? 1.2f*__expf(-1.f/u) : 0.f;
        const u64* W1p = (const u64*)sW1;
        const u64* B1p = (const u64*)sB1;
        #pragma unroll
        for (int k = 0; k < 8; k++) {
            const int h = g*16 + 2*k;
            u64 t2 = B1p[h >> 1];
            #pragma unroll
            for (int nb = 0; nb < 8; nb++)
                t2 = fma2(rbp[nb], W1p[(nb*64 + h) >> 1], t2);
            float ta, tb; unpack2(t2, ta, tb);
            const float h0 = env * __fdividef(ta, 1.f + __expf(-ta));
            const float h1 = env * __fdividef(tb, 1.f + __expf(-tb));
            *(float2*)(sH2 + (h >> 1)*256 + e*2) = make_float2(h0, h1);
        }
    }
}

// ---------------- edge kernel: software-pipelined tiles ----------------
__global__ __launch_bounds__(BLOCKE, 1)
void edge_kernel(const float* __restrict__ x,
                 const float* __restrict__ w1, const float* __restrict__ b1,
                 const float* __restrict__ w2, int has_v) {
    extern __shared__ float sm[];
    float* sW2 = sm + OFF_W2;
    float* sW1 = sm + OFF_W1;
    float* sB1 = sm + OFF_B1;

    const int tid  = threadIdx.x;
    const int lane = tid & 31;
    const int w    = tid >> 5;
    const int rcv  = blockIdx.x;
    const int pbase = w * 8;

    int cls;
    if      (w < 8)  cls = 0;
    else if (w < 10) cls = 1;
    else if (w < 18) cls = 2;
    else if (w < 20) cls = 3;
    else             cls = 4;
    const bool compute = has_v || cls == 0 || cls == 2;

    for (int i = tid; i < 512; i += BLOCKE) sW1[i] = w1[i];
    if (tid < 64) sB1[tid] = b1[tid];
    for (int i = tid; i < PP*64; i += BLOCKE) sW2[i] = w2[i];
    __syncthreads();

    const float xr0 = __ldg(&x[rcv*3+0]);
    const float xr1 = __ldg(&x[rcv*3+1]);
    const float xr2 = __ldg(&x[rcv*3+2]);

    float acc[24];
    #pragma unroll
    for (int i = 0; i < 24; i++) acc[i] = 0.f;

    // prologue: tile 0 into buffer 0
    produce_tile(sm, x, sW1, sB1, 0, rcv, xr0, xr1, xr2, tid, has_v);

    for (int tix = 0; tix < 6; tix++) {
        __syncthreads();     // buf(cur) complete; buf(nxt) free
        float* bufc = sm + (tix & 1) * BUF_F;
        float* bufn = sm + ((tix & 1) ^ 1) * BUF_F;
        if (tix < 5)
            produce_tile(bufn, x, sW1, sB1, (tix+1)*TILE, rcv, xr0, xr1, xr2, tid, has_v);
        if (!compute) continue;
        float* sH2  = bufc + F_H2;
        float* sEST = bufc + F_EST;
        float* sEVT = bufc + F_EVT;
        float* sRHT = bufc + F_RHT;
        u64 racc[16];   // [j 0..3 = p-pair][m 0..3 = edge lane+32m]
        #pragma unroll
        for (int i = 0; i < 16; i++) racc[i] = 0ull;
        #pragma unroll 4
        for (int kk = 0; kk < 32; kk++) {
            const float2* hp = (const float2*)(sH2 + kk*256) + lane;
            float2 f0 = hp[0], f1 = hp[32], f2v = hp[64], f3v = hp[96];
            const u64* w0 = (const u64*)(sW2 + (2*kk)*176 + pbase);
            const u64* w1r = (const u64*)(sW2 + (2*kk+1)*176 + pbase);
            ulonglong2 wA0 = *(const ulonglong2*)w0;
            ulonglong2 wB0 = *(const ulonglong2*)(w0 + 2);
            ulonglong2 wA1 = *(const ulonglong2*)w1r;
            ulonglong2 wB1 = *(const ulonglong2*)(w1r + 2);
            u64 d00 = pack2(f0.x, f0.x), d01 = pack2(f0.y, f0.y);
            u64 d10 = pack2(f1.x, f1.x), d11 = pack2(f1.y, f1.y);
            u64 d20 = pack2(f2v.x, f2v.x), d21 = pack2(f2v.y, f2v.y);
            u64 d30 = pack2(f3v.x, f3v.x), d31 = pack2(f3v.y, f3v.y);
            racc[0]  = fma2(d00, wA0.x, racc[0]);
            racc[1]  = fma2(d10, wA0.x, racc[1]);
            racc[2]  = fma2(d20, wA0.x, racc[2]);
            racc[3]  = fma2(d30, wA0.x, racc[3]);
            racc[4]  = fma2(d00, wA0.y, racc[4]);
            racc[5]  = fma2(d10, wA0.y, racc[5]);
            racc[6]  = fma2(d20, wA0.y, racc[6]);
            racc[7]  = fma2(d30, wA0.y, racc[7]);
            racc[8]  = fma2(d00, wB0.x, racc[8]);
            racc[9]  = fma2(d10, wB0.x, racc[9]);
            racc[10] = fma2(d20, wB0.x, racc[10]);
            racc[11] = fma2(d30, wB0.x, racc[11]);
            racc[12] = fma2(d00, wB0.y, racc[12]);
            racc[13] = fma2(d10, wB0.y, racc[13]);
            racc[14] = fma2(d20, wB0.y, racc[14]);
            racc[15] = fma2(d30, wB0.y, racc[15]);
            racc[0]  = fma2(d01, wA1.x, racc[0]);
            racc[1]  = fma2(d11, wA1.x, racc[1]);
            racc[2]  = fma2(d21, wA1.x, racc[2]);
            racc[3]  = fma2(d31, wA1.x, racc[3]);
            racc[4]  = fma2(d01, wA1.y, racc[4]);
            racc[5]  = fma2(d11, wA1.y, racc[5]);
            racc[6]  = fma2(d21, wA1.y, racc[6]);
            racc[7]  = fma2(d31, wA1.y, racc[7]);
            racc[8]  = fma2(d01, wB1.x, racc[8]);
            racc[9]  = fma2(d11, wB1.x, racc[9]);
            racc[10] = fma2(d21, wB1.x, racc[10]);
            racc[11] = fma2(d31, wB1.x, racc[11]);
            racc[12] = fma2(d01, wB1.y, racc[12]);
            racc[13] = fma2(d11, wB1.y, racc[13]);
            racc[14] = fma2(d21, wB1.y, racc[14]);
            racc[15] = fma2(d31, wB1.y, racc[15]);
        }
        #pragma unroll
        for (int m = 0; m < 4; m++) {
            const int le = lane + 32*m;
            if (cls == 0) {
                #pragma unroll
                for (int pj = 0; pj < 4; pj++) {
                    float R0, R1; unpack2(racc[pj*4+m], R0, R1);
                    acc[2*pj]   = fmaf(sEST[(pbase+2*pj)*128 + le],   R0, acc[2*pj]);
                    acc[2*pj+1] = fmaf(sEST[(pbase+2*pj+1)*128 + le], R1, acc[2*pj+1]);
                }
            } else if (cls == 1) {
                const float rx = sRHT[le], ry = sRHT[128+le], rz = sRHT[256+le];
                #pragma unroll
                for (int pj = 0; pj < 4; pj++) {
                    float R0, R1; unpack2(racc[pj*4+m], R0, R1);
                    const int i0 = pbase + 2*pj - 64;
                    float d0 = sEVT[(i0*3+0)*128+le]*rx + sEVT[(i0*3+1)*128+le]*ry + sEVT[(i0*3+2)*128+le]*rz;
                    float d1 = sEVT[((i0+1)*3+0)*128+le]*rx + sEVT[((i0+1)*3+1)*128+le]*ry + sEVT[((i0+1)*3+2)*128+le]*rz;
                    acc[2*pj]   = fmaf(d0, R0, acc[2*pj]);
                    acc[2*pj+1] = fmaf(d1, R1, acc[2*pj+1]);
                }
            } else if (cls == 2) {
                const float rx = sRHT[le], ry = sRHT[128+le], rz = sRHT[256+le];
                #pragma unroll
                for (int pj = 0; pj < 4; pj++) {
                    float R0, R1; unpack2(racc[pj*4+m], R0, R1);
                    const int i0 = pbase + 2*pj - 80;
                    const float t0_ = sEST[i0*128 + le] * R0;
                    const float t1_ = sEST[(i0+1)*128 + le] * R1;
                    acc[(2*pj)*3+0] = fmaf(t0_, rx, acc[(2*pj)*3+0]);
                    acc[(2*pj)*3+1] = fmaf(t0_, ry, acc[(2*pj)*3+1]);
                    acc[(2*pj)*3+2] = fmaf(t0_, rz, acc[(2*pj)*3+2]);
                    acc[(2*pj+1)*3+0] = fmaf(t1_, rx, acc[(2*pj+1)*3+0]);
                    acc[(2*pj+1)*3+1] = fmaf(t1_, ry, acc[(2*pj+1)*3+1]);
                    acc[(2*pj+1)*3+2] = fmaf(t1_, rz, acc[(2*pj+1)*3+2]);
                }
            } else if (cls == 3) {
                #pragma unroll
                for (int pj = 0; pj < 4; pj++) {
                    float R0, R1; unpack2(racc[pj*4+m], R0, R1);
                    const int i0 = pbase + 2*pj - 144;
                    #pragma unroll
                    for (int c = 0; c < 3; c++) {
                        acc[(2*pj)*3+c]   = fmaf(sEVT[(i0*3+c)*128+le],     R0, acc[(2*pj)*3+c]);
                        acc[(2*pj+1)*3+c] = fmaf(sEVT[((i0+1)*3+c)*128+le], R1, acc[(2*pj+1)*3+c]);
                    }
                }
            } else {
                const float rx = sRHT[le], ry = sRHT[128+le], rz = sRHT[256+le];
                #pragma unroll
                for (int pj = 0; pj < 4; pj++) {
                    float R0, R1; unpack2(racc[pj*4+m], R0, R1);
                    const int i0 = pbase + 2*pj - 160;
                    float e0x = sEVT[(i0*3+0)*128+le], e0y = sEVT[(i0*3+1)*128+le], e0z = sEVT[(i0*3+2)*128+le];
                    float e1x = sEVT[((i0+1)*3+0)*128+le], e1y = sEVT[((i0+1)*3+1)*128+le], e1z = sEVT[((i0+1)*3+2)*128+le];
                    acc[(2*pj)*3+0] = fmaf(e0y*rz - e0z*ry, R0, acc[(2*pj)*3+0]);
                    acc[(2*pj)*3+1] = fmaf(e0z*rx - e0x*rz, R0, acc[(2*pj)*3+1]);
                    acc[(2*pj)*3+2] = fmaf(e0x*ry - e0y*rx, R0, acc[(2*pj)*3+2]);
                    acc[(2*pj+1)*3+0] = fmaf(e1y*rz - e1z*ry, R1, acc[(2*pj+1)*3+0]);
                    acc[(2*pj+1)*3+1] = fmaf(e1z*rx - e1x*rz, R1, acc[(2*pj+1)*3+1]);
                    acc[(2*pj+1)*3+2] = fmaf(e1x*ry - e1y*rx, R1, acc[(2*pj+1)*3+2]);
                }
            }
        }
    }
    // warp butterfly over lanes (edge groups)
    #pragma unroll
    for (int i = 0; i < 24; i++) {
        #pragma unroll
        for (int o = 16; o > 0; o >>= 1)
            acc[i] += __shfl_xor_sync(0xffffffffu, acc[i], o);
    }
    if (lane == 0) {
        if (cls <= 1) {
            #pragma unroll
            for (int j = 0; j < 8; j++)
                g_aggs[rcv*80 + pbase + j] = acc[j] * AVGI;
        } else {
            const int rbase = (cls == 2) ? (pbase - 80) : (cls == 3 ? 64 + (pbase - 144) : 80 + (pbase - 160));
            #pragma unroll
            for (int j = 0; j < 8; j++) {
                const int base = rcv*288 + (rbase + j)*3;
                g_aggv[base+0] = acc[j*3+0] * AVGI;
                g_aggv[base+1] = acc[j*3+1] * AVGI;
                g_aggv[base+2] = acc[j*3+2] * AVGI;
            }
        }
    }
}

// ---------------- node update (+ fused next-layer transform) ----------------
__global__ void node_update(const float* __restrict__ wmix_s,
                            const float* __restrict__ wmix_v,
                            const float* __restrict__ wgate,
                            const float* __restrict__ wro_s,
                            const float* __restrict__ wro_v,
                            const float* __restrict__ wns_next,
                            const float* __restrict__ wnv_next,
                            float* __restrict__ out_s,
                            float* __restrict__ out_v,
                            int first, int last) {
    int n = blockIdx.x, t = threadIdx.x;   // 128 threads
    __shared__ float sA[80], sV[288], sM[64], sS[64], sG[16], sMV[48];
    if (t < 80) sA[t] = g_aggs[n*80 + t];
    for (int i = t; i < 288; i += 128) sV[i] = g_aggv[n*288 + i];
    __syncthreads();
    if (t < 64) {
        float m = 0.f;
        #pragma unroll
        for (int p = 0; p < 80; p++) m = fmaf(sA[p], wmix_s[p*64 + t], m);
        sM[t] = m;
        sS[t] = m / (1.f + __expf(-m));
    }
    if (t >= 64 && t < 112) {
        int i = t - 64, v = i/3, c = i - v*3;
        float m = 0.f;
        #pragma unroll
        for (int p = 0; p < 96; p++) m = fmaf(sV[p*3 + c], wmix_v[p*16 + v], m);
        sMV[i] = m;
    }
    __syncthreads();
    if (t < 16) {
        float g = 0.f;
        #pragma unroll
        for (int f = 0; f < 64; f++) g = fmaf(sM[f], wgate[f*16 + t], g);
        sG[t] = 1.f / (1.f + __expf(-g));
    }
    __syncthreads();
    if (t < 48) {
        int v = t/3;
        sMV[t] = sG[v] * sMV[t];
    }
    __syncthreads();
    // readouts
    if (t < 32) {
        float o = 0.f;
        #pragma unroll
        for (int f = 0; f < 64; f++) o = fmaf(sS[f], wro_s[f*32 + t], o);
        if (first) out_s[n*32 + t] = o; else out_s[n*32 + t] += o;
    }
    if (t >= 64 && t < 112) {
        int i = t - 64, k = i/3, c = i - k*3;
        float o = 0.f;
        #pragma unroll
        for (int v = 0; v < 16; v++) o = fmaf(sMV[v*3 + c], wro_v[v*16 + k], o);
        float prev = first ? 0.f : out_v[n*48 + i];
        o += prev;
        if (last) o += g_com[c];
        out_v[n*48 + i] = o;
    }
    // fused next-layer node transform (only when not last)
    if (!last) {
        if (t < 64) {
            float a = 0.f;
            #pragma unroll
            for (int k = 0; k < 64; k++) a = fmaf(sS[k], wns_next[k*64 + t], a);
            g_hsT[t*NN + n] = a;
        }
        if (t >= 64 && t < 112) {
            int i = t - 64, wv = i/3, c = i - wv*3;
            float a = 0.f;
            #pragma unroll
            for (int v = 0; v < 16; v++) a = fmaf(sMV[v*3 + c], wnv_next[v*16 + wv], a);
            g_hvT[i*NN + n] = a;
        }
    }
}

// ---------------- launch ----------------
extern "C" void kernel_launch(void* const* d_in, const int* in_sizes, int n_in,
                              void* d_out, int out_size) {
    const float* x      = (const float*)d_in[0];
    const float* embed  = (const float*)d_in[1];
    const float* wns    = (const float*)d_in[2];
    const float* wnv    = (const float*)d_in[3];
    const float* wr1    = (const float*)d_in[4];
    const float* br1    = (const float*)d_in[5];
    const float* wr2    = (const float*)d_in[6];
    const float* wmixs  = (const float*)d_in[7];
    const float* wmixv  = (const float*)d_in[8];
    const float* wgate  = (const float*)d_in[9];
    const float* wros   = (const float*)d_in[10];
    const float* wrov   = (const float*)d_in[11];

    float* out   = (float*)d_out;
    float* out_s = out;
    float* out_v = out + NN*ROS;

    cudaFuncSetAttribute(edge_kernel,
        cudaFuncAttributeMaxDynamicSharedMemorySize, SMEM_BYTES);

    prep0<<<1, NN>>>(x, embed, wns);   // com + layer-0 transform (broadcast h)

    for (int t = 0; t < TT; t++) {
        edge_kernel<<<NN, BLOCKE, SMEM_BYTES>>>(
            x, wr1 + t*NB*HR, br1 + t*HR, wr2 + t*HR*PP, (t == 0) ? 0 : 1);
        node_update<<<NN, 128>>>(
            wmixs + t*80*64, wmixv + t*96*16, wgate + t*64*16,
            wros + t*64*32, wrov + t*16*16,
            wns + ((t+1) % TT)*FF*FF, wnv + ((t+1) % TT)*VV*VV,
            out_s, out_v, (t == 0) ? 1 : 0, (t == TT-1) ? 1 : 0);
    }
}

// round 10
// speedup vs baseline: 1.0323x; 1.0323x over previous
#include <cuda_runtime.h>
#include <cuda_bf16.h>
#include <math.h>
#include <stdint.h>

// ---------------- problem constants ----------------
#define NN   768
#define FF   64
#define VV   16
#define NB   8
#define HR   64
#define TT   2
#define ROS  32
#define ROV  16
#define PP   176
#define AVGI (1.0f/767.0f)

#define TILE   128
#define BLOCKE 704        // 22 warps: one warp per 8 p-columns

// shared memory float offsets (R6 layout)
#define OFF_H2    0            // [32][128][2] k-interleaved H : 8192 floats
#define OFF_EST   8192         // [64][128]
#define OFF_EVT   16384        // [48][128]
#define OFF_RHT   22528        // [3][128]
#define OFF_W2    22912        // [64][176]
#define OFF_W1    34176        // [8][64]
#define OFF_B1    34688        // [64]
#define OFF_X     34752        // [768*3]
#define SMEM_FLOATS 37056
#define SMEM_BYTES  (SMEM_FLOATS*4)

typedef unsigned long long u64;

__device__ __forceinline__ u64 pack2(float lo, float hi) {
    u64 r; asm("mov.b64 %0,{%1,%2};" : "=l"(r) : "f"(lo), "f"(hi)); return r;
}
__device__ __forceinline__ void unpack2(u64 v, float& lo, float& hi) {
    asm("mov.b64 {%0,%1},%2;" : "=f"(lo), "=f"(hi) : "l"(v));
}
__device__ __forceinline__ u64 fma2(u64 a, u64 b, u64 c) {
    u64 d; asm("fma.rn.f32x2 %0,%1,%2,%3;" : "=l"(d) : "l"(a), "l"(b), "l"(c)); return d;
}

// ---------------- device scratch ----------------
__device__ float g_hsT[FF*NN];      // transposed: [f][node]
__device__ float g_hvT[48*NN];
__device__ float g_aggs[NN*80];
__device__ float g_aggv[NN*288];
__device__ float g_com[3];

// ---------------- prep0: com + layer-0 transform (broadcast) ----------------
__global__ void prep0(const float* __restrict__ x,
                      const float* __restrict__ embed,
                      const float* __restrict__ wns0) {
    __shared__ float s0[24], s1[24], s2[24], sE[64];
    int i = threadIdx.x;           // 768 threads
    float v0 = x[i*3+0], v1 = x[i*3+1], v2 = x[i*3+2];
    #pragma unroll
    for (int o = 16; o > 0; o >>= 1) {
        v0 += __shfl_down_sync(0xffffffffu, v0, o);
        v1 += __shfl_down_sync(0xffffffffu, v1, o);
        v2 += __shfl_down_sync(0xffffffffu, v2, o);
    }
    if ((i & 31) == 0) { s0[i>>5]=v0; s1[i>>5]=v1; s2[i>>5]=v2; }
    if (i < 64) {
        float a = 0.f;
        #pragma unroll
        for (int k = 0; k < 64; k++) a = fmaf(embed[k], wns0[k*64 + i], a);
        sE[i] = a;
    }
    __syncthreads();
    if (i == 0) {
        float a0=0,a1=0,a2=0;
        for (int w = 0; w < 24; w++) { a0+=s0[w]; a1+=s1[w]; a2+=s2[w]; }
        g_com[0]=a0/768.f; g_com[1]=a1/768.f; g_com[2]=a2/768.f;
    }
    for (int j = i; j < 64*NN; j += 768) g_hsT[j] = sE[j / NN];
    for (int j = i; j < 48*NN; j += 768) g_hvT[j] = 0.f;
}

// ---------------- edge kernel (R6 structure, verbatim) ----------------
__global__ __launch_bounds__(BLOCKE, 1)
void edge_kernel(const float* __restrict__ x,
                 const float* __restrict__ w1, const float* __restrict__ b1,
                 const float* __restrict__ w2, int has_v) {
    extern __shared__ float sm[];
    float* sH2  = sm + OFF_H2;              // [32][128][2]
    float* sEST = sm + OFF_EST;             // [64][128]
    float* sEVT = sm + OFF_EVT;             // [48][128]
    float* sRHT = sm + OFF_RHT;             // [3][128]
    float* sW2  = sm + OFF_W2;              // [64][176]
    float* sW1  = sm + OFF_W1;              // [8][64]
    float* sB1  = sm + OFF_B1;              // [64]
    float* sX   = sm + OFF_X;               // [768*3]

    const int tid  = threadIdx.x;
    const int lane = tid & 31;
    const int w    = tid >> 5;              // warp 0..21 = p-group
    const int rcv  = blockIdx.x;
    const int pbase = w * 8;

    int cls;
    if      (w < 8)  cls = 0;
    else if (w < 10) cls = 1;
    else if (w < 18) cls = 2;
    else if (w < 20) cls = 3;
    else             cls = 4;
    const bool compute = has_v || cls == 0 || cls == 2;

    for (int i = tid; i < 512; i += BLOCKE) sW1[i] = w1[i];
    if (tid < 64) sB1[tid] = b1[tid];
    for (int i = tid; i < PP*64; i += BLOCKE) sW2[i] = w2[i];
    for (int i = tid; i < NN*3; i += BLOCKE) sX[i] = x[i];
    __syncthreads();

    const float xr0 = sX[rcv*3+0], xr1 = sX[rcv*3+1], xr2 = sX[rcv*3+2];

    float acc[24];
    #pragma unroll
    for (int i = 0; i < 24; i++) acc[i] = 0.f;

    for (int t0 = 0; t0 < NN; t0 += TILE) {
        __syncthreads();
        for (int i = tid; i < 64*TILE; i += BLOCKE) {
            int f = i >> 7, e = i & 127;
            sEST[i] = g_hsT[f*NN + t0 + e];
        }
        if (has_v) {
            for (int i = tid; i < 48*TILE; i += BLOCKE) {
                int f = i >> 7, e = i & 127;
                sEVT[i] = g_hvT[f*NN + t0 + e];
            }
        }
        if (tid < 512) {
            const int e  = tid & 127;
            const int g  = tid >> 7;
            const int s  = t0 + e;
            const float vx = xr0 - sX[s*3+0];
            const float vy = xr1 - sX[s*3+1];
            const float vz = xr2 - sX[s*3+2];
            const float rr = sqrtf(vx*vx + vy*vy + vz*vz);
            const bool self = (s == rcv);
            const float rinv = self ? 0.f : (1.f / rr);
            if (g == 0) {
                sRHT[0*128+e] = vx*rinv;
                sRHT[1*128+e] = vy*rinv;
                sRHT[2*128+e] = vz*rinv;
            }
            const float rg = self ? 1.f : rr;
            float sa, ca;
            __sincosf(0.31415926535f * rg, &sa, &ca);
            const float coef = 0.4472135955f * rinv;
            u64 rbp[8];
            {
                float sp = 0.f, sc = sa;
                const float twoc = 2.f*ca;
                #pragma unroll
                for (int nb = 0; nb < 8; nb++) {
                    float rb = sc * coef;
                    rbp[nb] = pack2(rb, rb);
                    float sn = fmaf(twoc, sc, -sp);
                    sp = sc; sc = sn;
                }
            }
            const float u = 2.f * (1.f - rr*0.1f);
            const float env = (!self && u > 0.f) ? 1.2f*__expf(-1.f/u) : 0.f;
            const u64* W1p = (const u64*)sW1;
            const u64* B1p = (const u64*)sB1;
            #pragma unroll
            for (int k = 0; k < 8; k++) {
                const int h = g*16 + 2*k;
                u64 t2 = B1p[h >> 1];
                #pragma unroll
                for (int nb = 0; nb < 8; nb++)
                    t2 = fma2(rbp[nb], W1p[(nb*64 + h) >> 1], t2);
                float ta, tb; unpack2(t2, ta, tb);
                const float h0 = env * __fdividef(ta, 1.f + __expf(-ta));
                const float h1 = env * __fdividef(tb, 1.f + __expf(-tb));
                *(float2*)(sH2 + (h >> 1)*256 + e*2) = make_float2(h0, h1);
            }
        }
        __syncthreads();
        if (compute) {
            u64 racc[16];
            #pragma unroll
            for (int i = 0; i < 16; i++) racc[i] = 0ull;
            #pragma unroll 4
            for (int kk = 0; kk < 32; kk++) {
                const float2* hp = (const float2*)(sH2 + kk*256) + lane;
                float2 f0 = hp[0], f1 = hp[32], f2v = hp[64], f3v = hp[96];
                const u64* w0 = (const u64*)(sW2 + (2*kk)*176 + pbase);
                const u64* w1r = (const u64*)(sW2 + (2*kk+1)*176 + pbase);
                ulonglong2 wA0 = *(const ulonglong2*)w0;
                ulonglong2 wB0 = *(const ulonglong2*)(w0 + 2);
                ulonglong2 wA1 = *(const ulonglong2*)w1r;
                ulonglong2 wB1 = *(const ulonglong2*)(w1r + 2);
                u64 d00 = pack2(f0.x, f0.x), d01 = pack2(f0.y, f0.y);
                u64 d10 = pack2(f1.x, f1.x), d11 = pack2(f1.y, f1.y);
                u64 d20 = pack2(f2v.x, f2v.x), d21 = pack2(f2v.y, f2v.y);
                u64 d30 = pack2(f3v.x, f3v.x), d31 = pack2(f3v.y, f3v.y);
                racc[0]  = fma2(d00, wA0.x, racc[0]);
                racc[1]  = fma2(d10, wA0.x, racc[1]);
                racc[2]  = fma2(d20, wA0.x, racc[2]);
                racc[3]  = fma2(d30, wA0.x, racc[3]);
                racc[4]  = fma2(d00, wA0.y, racc[4]);
                racc[5]  = fma2(d10, wA0.y, racc[5]);
                racc[6]  = fma2(d20, wA0.y, racc[6]);
                racc[7]  = fma2(d30, wA0.y, racc[7]);
                racc[8]  = fma2(d00, wB0.x, racc[8]);
                racc[9]  = fma2(d10, wB0.x, racc[9]);
                racc[10] = fma2(d20, wB0.x, racc[10]);
                racc[11] = fma2(d30, wB0.x, racc[11]);
                racc[12] = fma2(d00, wB0.y, racc[12]);
                racc[13] = fma2(d10, wB0.y, racc[13]);
                racc[14] = fma2(d20, wB0.y, racc[14]);
                racc[15] = fma2(d30, wB0.y, racc[15]);
                racc[0]  = fma2(d01, wA1.x, racc[0]);
                racc[1]  = fma2(d11, wA1.x, racc[1]);
                racc[2]  = fma2(d21, wA1.x, racc[2]);
                racc[3]  = fma2(d31, wA1.x, racc[3]);
                racc[4]  = fma2(d01, wA1.y, racc[4]);
                racc[5]  = fma2(d11, wA1.y, racc[5]);
                racc[6]  = fma2(d21, wA1.y, racc[6]);
                racc[7]  = fma2(d31, wA1.y, racc[7]);
                racc[8]  = fma2(d01, wB1.x, racc[8]);
                racc[9]  = fma2(d11, wB1.x, racc[9]);
                racc[10] = fma2(d21, wB1.x, racc[10]);
                racc[11] = fma2(d31, wB1.x, racc[11]);
                racc[12] = fma2(d01, wB1.y, racc[12]);
                racc[13] = fma2(d11, wB1.y, racc[13]);
                racc[14] = fma2(d21, wB1.y, racc[14]);
                racc[15] = fma2(d31, wB1.y, racc[15]);
            }
            #pragma unroll
            for (int m = 0; m < 4; m++) {
                const int le = lane + 32*m;
                if (cls == 0) {
                    #pragma unroll
                    for (int pj = 0; pj < 4; pj++) {
                        float R0, R1; unpack2(racc[pj*4+m], R0, R1);
                        acc[2*pj]   = fmaf(sEST[(pbase+2*pj)*128 + le],   R0, acc[2*pj]);
                        acc[2*pj+1] = fmaf(sEST[(pbase+2*pj+1)*128 + le], R1, acc[2*pj+1]);
                    }
                } else if (cls == 1) {
                    const float rx = sRHT[le], ry = sRHT[128+le], rz = sRHT[256+le];
                    #pragma unroll
                    for (int pj = 0; pj < 4; pj++) {
                        float R0, R1; unpack2(racc[pj*4+m], R0, R1);
                        const int i0 = pbase + 2*pj - 64;
                        float d0 = sEVT[(i0*3+0)*128+le]*rx + sEVT[(i0*3+1)*128+le]*ry + sEVT[(i0*3+2)*128+le]*rz;
                        float d1 = sEVT[((i0+1)*3+0)*128+le]*rx + sEVT[((i0+1)*3+1)*128+le]*ry + sEVT[((i0+1)*3+2)*128+le]*rz;
                        acc[2*pj]   = fmaf(d0, R0, acc[2*pj]);
                        acc[2*pj+1] = fmaf(d1, R1, acc[2*pj+1]);
                    }
                } else if (cls == 2) {
                    const float rx = sRHT[le], ry = sRHT[128+le], rz = sRHT[256+le];
                    #pragma unroll
                    for (int pj = 0; pj < 4; pj++) {
                        float R0, R1; unpack2(racc[pj*4+m], R0, R1);
                        const int i0 = pbase + 2*pj - 80;
                        const float t0_ = sEST[i0*128 + le] * R0;
                        const float t1_ = sEST[(i0+1)*128 + le] * R1;
                        acc[(2*pj)*3+0] = fmaf(t0_, rx, acc[(2*pj)*3+0]);
                        acc[(2*pj)*3+1] = fmaf(t0_, ry, acc[(2*pj)*3+1]);
                        acc[(2*pj)*3+2] = fmaf(t0_, rz, acc[(2*pj)*3+2]);
                        acc[(2*pj+1)*3+0] = fmaf(t1_, rx, acc[(2*pj+1)*3+0]);
                        acc[(2*pj+1)*3+1] = fmaf(t1_, ry, acc[(2*pj+1)*3+1]);
                        acc[(2*pj+1)*3+2] = fmaf(t1_, rz, acc[(2*pj+1)*3+2]);
                    }
                } else if (cls == 3) {
                    #pragma unroll
                    for (int pj = 0; pj < 4; pj++) {
                        float R0, R1; unpack2(racc[pj*4+m], R0, R1);
                        const int i0 = pbase + 2*pj - 144;
                        #pragma unroll
                        for (int c = 0; c < 3; c++) {
                            acc[(2*pj)*3+c]   = fmaf(sEVT[(i0*3+c)*128+le],     R0, acc[(2*pj)*3+c]);
                            acc[(2*pj+1)*3+c] = fmaf(sEVT[((i0+1)*3+c)*128+le], R1, acc[(2*pj+1)*3+c]);
                        }
                    }
                } else {
                    const float rx = sRHT[le], ry = sRHT[128+le], rz = sRHT[256+le];
                    #pragma unroll
                    for (int pj = 0; pj < 4; pj++) {
                        float R0, R1; unpack2(racc[pj*4+m], R0, R1);
                        const int i0 = pbase + 2*pj - 160;
                        float e0x = sEVT[(i0*3+0)*128+le], e0y = sEVT[(i0*3+1)*128+le], e0z = sEVT[(i0*3+2)*128+le];
                        float e1x = sEVT[((i0+1)*3+0)*128+le], e1y = sEVT[((i0+1)*3+1)*128+le], e1z = sEVT[((i0+1)*3+2)*128+le];
                        acc[(2*pj)*3+0] = fmaf(e0y*rz - e0z*ry, R0, acc[(2*pj)*3+0]);
                        acc[(2*pj)*3+1] = fmaf(e0z*rx - e0x*rz, R0, acc[(2*pj)*3+1]);
                        acc[(2*pj)*3+2] = fmaf(e0x*ry - e0y*rx, R0, acc[(2*pj)*3+2]);
                        acc[(2*pj+1)*3+0] = fmaf(e1y*rz - e1z*ry, R1, acc[(2*pj+1)*3+0]);
                        acc[(2*pj+1)*3+1] = fmaf(e1z*rx - e1x*rz, R1, acc[(2*pj+1)*3+1]);
                        acc[(2*pj+1)*3+2] = fmaf(e1x*ry - e1y*rx, R1, acc[(2*pj+1)*3+2]);
                    }
                }
            }
        }
    }
    #pragma unroll
    for (int i = 0; i < 24; i++) {
        #pragma unroll
        for (int o = 16; o > 0; o >>= 1)
            acc[i] += __shfl_xor_sync(0xffffffffu, acc[i], o);
    }
    if (lane == 0) {
        if (cls <= 1) {
            #pragma unroll
            for (int j = 0; j < 8; j++)
                g_aggs[rcv*80 + pbase + j] = acc[j] * AVGI;
        } else {
            const int rbase = (cls == 2) ? (pbase - 80) : (cls == 3 ? 64 + (pbase - 144) : 80 + (pbase - 160));
            #pragma unroll
            for (int j = 0; j < 8; j++) {
                const int base = rcv*288 + (rbase + j)*3;
                g_aggv[base+0] = acc[j*3+0] * AVGI;
                g_aggv[base+1] = acc[j*3+1] * AVGI;
                g_aggv[base+2] = acc[j*3+2] * AVGI;
            }
        }
    }
}

// ---------------- node update (+ fused next-layer transform) ----------------
__global__ void node_update(const float* __restrict__ wmix_s,
                            const float* __restrict__ wmix_v,
                            const float* __restrict__ wgate,
                            const float* __restrict__ wro_s,
                            const float* __restrict__ wro_v,
                            const float* __restrict__ wns_next,
                            const float* __restrict__ wnv_next,
                            float* __restrict__ out_s,
                            float* __restrict__ out_v,
                            int first, int last) {
    int n = blockIdx.x, t = threadIdx.x;   // 128 threads
    __shared__ float sA[80], sV[288], sM[64], sS[64], sG[16], sMV[48];
    if (t < 80) sA[t] = g_aggs[n*80 + t];
    for (int i = t; i < 288; i += 128) sV[i] = g_aggv[n*288 + i];
    __syncthreads();
    if (t < 64) {
        float m = 0.f;
        #pragma unroll
        for (int p = 0; p < 80; p++) m = fmaf(sA[p], wmix_s[p*64 + t], m);
        sM[t] = m;
        sS[t] = m / (1.f + __expf(-m));
    }
    if (t >= 64 && t < 112) {
        int i = t - 64, v = i/3, c = i - v*3;
        float m = 0.f;
        #pragma unroll
        for (int p = 0; p < 96; p++) m = fmaf(sV[p*3 + c], wmix_v[p*16 + v], m);
        sMV[i] = m;
    }
    __syncthreads();
    if (t < 16) {
        float g = 0.f;
        #pragma unroll
        for (int f = 0; f < 64; f++) g = fmaf(sM[f], wgate[f*16 + t], g);
        sG[t] = 1.f / (1.f + __expf(-g));
    }
    __syncthreads();
    if (t < 48) {
        int v = t/3;
        sMV[t] = sG[v] * sMV[t];
    }
    __syncthreads();
    if (t < 32) {
        float o = 0.f;
        #pragma unroll
        for (int f = 0; f < 64; f++) o = fmaf(sS[f], wro_s[f*32 + t], o);
        if (first) out_s[n*32 + t] = o; else out_s[n*32 + t] += o;
    }
    if (t >= 64 && t < 112) {
        int i = t - 64, k = i/3, c = i - k*3;
        float o = 0.f;
        #pragma unroll
        for (int v = 0; v < 16; v++) o = fmaf(sMV[v*3 + c], wro_v[v*16 + k], o);
        float prev = first ? 0.f : out_v[n*48 + i];
        o += prev;
        if (last) o += g_com[c];
        out_v[n*48 + i] = o;
    }
    if (!last) {
        if (t < 64) {
            float a = 0.f;
            #pragma unroll
            for (int k = 0; k < 64; k++) a = fmaf(sS[k], wns_next[k*64 + t], a);
            g_hsT[t*NN + n] = a;
        }
        if (t >= 64 && t < 112) {
            int i = t - 64, wv = i/3, c = i - wv*3;
            float a = 0.f;
            #pragma unroll
            for (int v = 0; v < 16; v++) a = fmaf(sMV[v*3 + c], wnv_next[v*16 + wv], a);
            g_hvT[i*NN + n] = a;
        }
    }
}

// ---------------- launch ----------------
extern "C" void kernel_launch(void* const* d_in, const int* in_sizes, int n_in,
                              void* d_out, int out_size) {
    const float* x      = (const float*)d_in[0];
    const float* embed  = (const float*)d_in[1];
    const float* wns    = (const float*)d_in[2];
    const float* wnv    = (const float*)d_in[3];
    const float* wr1    = (const float*)d_in[4];
    const float* br1    = (const float*)d_in[5];
    const float* wr2    = (const float*)d_in[6];
    const float* wmixs  = (const float*)d_in[7];
    const float* wmixv  = (const float*)d_in[8];
    const float* wgate  = (const float*)d_in[9];
    const float* wros   = (const float*)d_in[10];
    const float* wrov   = (const float*)d_in[11];

    float* out   = (float*)d_out;
    float* out_s = out;
    float* out_v = out + NN*ROS;

    cudaFuncSetAttribute(edge_kernel,
        cudaFuncAttributeMaxDynamicSharedMemorySize, SMEM_BYTES);

    prep0<<<1, NN>>>(x, embed, wns);

    for (int t = 0; t < TT; t++) {
        edge_kernel<<<NN, BLOCKE, SMEM_BYTES>>>(
            x, wr1 + t*NB*HR, br1 + t*HR, wr2 + t*HR*PP, (t == 0) ? 0 : 1);
        node_update<<<NN, 128>>>(
            wmixs + t*80*64, wmixv + t*96*16, wgate + t*64*16,
            wros + t*64*32, wrov + t*16*16,
            wns + ((t+1) % TT)*FF*FF, wnv + ((t+1) % TT)*VV*VV,
            out_s, out_v, (t == 0) ? 1 : 0, (t == TT-1) ? 1 : 0);
    }
}

// round 11
// speedup vs baseline: 1.5618x; 1.5129x over previous
#include <cuda_runtime.h>
#include <cuda_bf16.h>
#include <math.h>
#include <stdint.h>

// ---------------- problem constants ----------------
#define NN   768
#define FF   64
#define VV   16
#define NB   8
#define HR   64
#define TT   2
#define ROS  32
#define ROV  16
#define PP   176
#define AVGI (1.0f/767.0f)

#define TILE   128
#define BLOCKE 704        // layer-1 edge kernel: 22 warps

// layer-1 shared memory float offsets (R6 layout)
#define OFF_H2    0            // [32][128][2]
#define OFF_EST   8192         // [64][128]
#define OFF_EVT   16384        // [48][128]
#define OFF_RHT   22528        // [3][128] (pad to 384? uses 384)
#define OFF_W2    22912        // [64][176]
#define OFF_W1    34176        // [8][64]
#define OFF_B1    34688        // [64]
#define OFF_X     34752        // [768*3]
#define SMEM_FLOATS 37056
#define SMEM_BYTES  (SMEM_FLOATS*4)

// layer-0 shared memory float offsets
#define Z_H2    0              // [32][128][2] : 8192
#define Z_RHT   8192           // [3][128] + pad : 512
#define Z_W1    8704           // 512
#define Z_B1    9216           // 64
#define Z_ES0   9280           // 64
#define Z_SUM   9344           // [4][64] : 256
#define Z_X     9600           // 2304
#define Z_W2    11904          // [64][176] : 11264
#define SMEM0_FLOATS 23168
#define SMEM0_BYTES  (SMEM0_FLOATS*4)   // 92672

typedef unsigned long long u64;

__device__ __forceinline__ u64 pack2(float lo, float hi) {
    u64 r; asm("mov.b64 %0,{%1,%2};" : "=l"(r) : "f"(lo), "f"(hi)); return r;
}
__device__ __forceinline__ void unpack2(u64 v, float& lo, float& hi) {
    asm("mov.b64 {%0,%1},%2;" : "=f"(lo), "=f"(hi) : "l"(v));
}
__device__ __forceinline__ u64 fma2(u64 a, u64 b, u64 c) {
    u64 d; asm("fma.rn.f32x2 %0,%1,%2,%3;" : "=l"(d) : "l"(a), "l"(b), "l"(c)); return d;
}

// ---------------- device scratch ----------------
__device__ float g_hsT[FF*NN];      // transposed: [f][node]
__device__ float g_hvT[48*NN];
__device__ float g_hs0[FF];         // layer-0 broadcast es
__device__ float g_aggs[NN*80];
__device__ float g_aggv[NN*288];
__device__ float g_com[3];

// ---------------- prep0: com + layer-0 transform (broadcast) ----------------
__global__ void prep0(const float* __restrict__ x,
                      const float* __restrict__ embed,
                      const float* __restrict__ wns0) {
    __shared__ float s0[24], s1[24], s2[24], sE[64];
    int i = threadIdx.x;           // 768 threads
    float v0 = x[i*3+0], v1 = x[i*3+1], v2 = x[i*3+2];
    #pragma unroll
    for (int o = 16; o > 0; o >>= 1) {
        v0 += __shfl_down_sync(0xffffffffu, v0, o);
        v1 += __shfl_down_sync(0xffffffffu, v1, o);
        v2 += __shfl_down_sync(0xffffffffu, v2, o);
    }
    if ((i & 31) == 0) { s0[i>>5]=v0; s1[i>>5]=v1; s2[i>>5]=v2; }
    if (i < 64) {
        float a = 0.f;
        #pragma unroll
        for (int k = 0; k < 64; k++) a = fmaf(embed[k], wns0[k*64 + i], a);
        sE[i] = a;
        g_hs0[i] = a;
    }
    __syncthreads();
    if (i == 0) {
        float a0=0,a1=0,a2=0;
        for (int w = 0; w < 24; w++) { a0+=s0[w]; a1+=s1[w]; a2+=s2[w]; }
        g_com[0]=a0/768.f; g_com[1]=a1/768.f; g_com[2]=a2/768.f;
    }
    // g_hsT for layer0 not needed (collapsed kernel), but harmless to skip
    for (int j = i; j < 48*NN; j += 768) g_hvT[j] = 0.f;
}

// ---------------- layer-0 edge kernel: collapsed sums ----------------
__global__ __launch_bounds__(512, 2)
void edge0_kernel(const float* __restrict__ x,
                  const float* __restrict__ w1, const float* __restrict__ b1,
                  const float* __restrict__ w2) {
    extern __shared__ float sm[];
    float* sH2  = sm + Z_H2;
    float* sRHT = sm + Z_RHT;
    float* sW1  = sm + Z_W1;
    float* sB1  = sm + Z_B1;
    float* sES0 = sm + Z_ES0;
    float* sSUM = sm + Z_SUM;
    float* sX   = sm + Z_X;
    float* sW2  = sm + Z_W2;

    const int tid  = threadIdx.x;
    const int lane = tid & 31;
    const int w    = tid >> 5;      // 0..15
    const int rcv  = blockIdx.x;

    for (int i = tid; i < 512; i += 512) sW1[i] = w1[i];
    if (tid < 64) { sB1[tid] = b1[tid]; sES0[tid] = g_hs0[tid]; }
    for (int i = tid; i < PP*64; i += 512) sW2[i] = w2[i];
    for (int i = tid; i < NN*3; i += 512) sX[i] = x[i];
    __syncthreads();

    const float xr0 = sX[rcv*3+0], xr1 = sX[rcv*3+1], xr2 = sX[rcv*3+2];

    // sum accumulators: warp -> (type = w&3, kp-range = (w>>2)*8 .. +8)
    const int styp = w & 3;         // 0: plain, 1..3: rhat component
    const int kpb  = (w >> 2) * 8;  // 8 k-pairs of 2 k's
    u64 acc[8];
    #pragma unroll
    for (int i = 0; i < 8; i++) acc[i] = 0ull;

    for (int t0 = 0; t0 < NN; t0 += TILE) {
        __syncthreads();
        // ---- phase 1: all 512 threads; edge = tid&127, h-group = tid>>7 ----
        {
            const int e  = tid & 127;
            const int g  = tid >> 7;
            const int s  = t0 + e;
            const float vx = xr0 - sX[s*3+0];
            const float vy = xr1 - sX[s*3+1];
            const float vz = xr2 - sX[s*3+2];
            const float rr = sqrtf(vx*vx + vy*vy + vz*vz);
            const bool self = (s == rcv);
            const float rinv = self ? 0.f : (1.f / rr);
            if (g == 0) {
                sRHT[0*128+e] = vx*rinv;
                sRHT[1*128+e] = vy*rinv;
                sRHT[2*128+e] = vz*rinv;
            }
            const float rg = self ? 1.f : rr;
            float sa, ca;
            __sincosf(0.31415926535f * rg, &sa, &ca);
            const float coef = 0.4472135955f * rinv;
            u64 rbp[8];
            {
                float sp = 0.f, sc = sa;
                const float twoc = 2.f*ca;
                #pragma unroll
                for (int nb = 0; nb < 8; nb++) {
                    float rb = sc * coef;
                    rbp[nb] = pack2(rb, rb);
                    float sn = fmaf(twoc, sc, -sp);
                    sp = sc; sc = sn;
                }
            }
            const float u = 2.f * (1.f - rr*0.1f);
            const float env = (!self && u > 0.f) ? 1.2f*__expf(-1.f/u) : 0.f;
            const u64* W1p = (const u64*)sW1;
            const u64* B1p = (const u64*)sB1;
            #pragma unroll
            for (int k = 0; k < 8; k++) {
                const int h = g*16 + 2*k;
                u64 t2 = B1p[h >> 1];
                #pragma unroll
                for (int nb = 0; nb < 8; nb++)
                    t2 = fma2(rbp[nb], W1p[(nb*64 + h) >> 1], t2);
                float ta, tb; unpack2(t2, ta, tb);
                const float h0 = env * __fdividef(ta, 1.f + __expf(-ta));
                const float h1 = env * __fdividef(tb, 1.f + __expf(-tb));
                *(float2*)(sH2 + (h >> 1)*256 + e*2) = make_float2(h0, h1);
            }
        }
        __syncthreads();
        // ---- phase 2: weighted H sums ----
        #pragma unroll
        for (int m = 0; m < 4; m++) {
            const int le = lane + 32*m;
            const float wt = (styp == 0) ? 1.f : sRHT[(styp-1)*128 + le];
            const u64 wd = pack2(wt, wt);
            #pragma unroll
            for (int kp = 0; kp < 8; kp++) {
                u64 hv = *(const u64*)(sH2 + (kpb + kp)*256 + le*2);
                acc[kp] = fma2(hv, wd, acc[kp]);
            }
        }
    }
    // reduce over lanes, write sSUM[styp][k]
    {
        float a0[8], a1[8];
        #pragma unroll
        for (int kp = 0; kp < 8; kp++) unpack2(acc[kp], a0[kp], a1[kp]);
        #pragma unroll
        for (int kp = 0; kp < 8; kp++) {
            #pragma unroll
            for (int o = 16; o > 0; o >>= 1) {
                a0[kp] += __shfl_xor_sync(0xffffffffu, a0[kp], o);
                a1[kp] += __shfl_xor_sync(0xffffffffu, a1[kp], o);
            }
        }
        if (lane == 0) {
            #pragma unroll
            for (int kp = 0; kp < 8; kp++) {
                sSUM[styp*64 + (kpb+kp)*2 + 0] = a0[kp];
                sSUM[styp*64 + (kpb+kp)*2 + 1] = a1[kp];
            }
        }
    }
    __syncthreads();
    // ---- final GEMV + scatter ----
    if (tid < 256) {
        const int t = tid >> 6;        // 0: cls0, 1..3: cls2 component
        const int pr = tid & 63;
        const int p = (t == 0) ? pr : (80 + pr);
        const float* S = sSUM + t*64;
        float dot = 0.f;
        #pragma unroll
        for (int k = 0; k < 64; k++) dot = fmaf(S[k], sW2[k*176 + p], dot);
        const float v = sES0[pr] * dot * AVGI;
        if (t == 0) g_aggs[rcv*80 + pr] = v;
        else        g_aggv[rcv*288 + pr*3 + (t-1)] = v;
    } else if (tid < 272) {
        g_aggs[rcv*80 + 64 + (tid - 256)] = 0.f;   // cls1 zero (h_v = 0)
    } else if (tid < 368) {
        g_aggv[rcv*288 + 192 + (tid - 272)] = 0.f; // cls3/4 zero
    }
}

// ---------------- layer-1 edge kernel (R6 structure, verbatim) ----------------
__global__ __launch_bounds__(BLOCKE, 1)
void edge_kernel(const float* __restrict__ x,
                 const float* __restrict__ w1, const float* __restrict__ b1,
                 const float* __restrict__ w2) {
    extern __shared__ float sm[];
    float* sH2  = sm + OFF_H2;
    float* sEST = sm + OFF_EST;
    float* sEVT = sm + OFF_EVT;
    float* sRHT = sm + OFF_RHT;
    float* sW2  = sm + OFF_W2;
    float* sW1  = sm + OFF_W1;
    float* sB1  = sm + OFF_B1;
    float* sX   = sm + OFF_X;

    const int tid  = threadIdx.x;
    const int lane = tid & 31;
    const int w    = tid >> 5;
    const int rcv  = blockIdx.x;
    const int pbase = w * 8;

    int cls;
    if      (w < 8)  cls = 0;
    else if (w < 10) cls = 1;
    else if (w < 18) cls = 2;
    else if (w < 20) cls = 3;
    else             cls = 4;

    for (int i = tid; i < 512; i += BLOCKE) sW1[i] = w1[i];
    if (tid < 64) sB1[tid] = b1[tid];
    for (int i = tid; i < PP*64; i += BLOCKE) sW2[i] = w2[i];
    for (int i = tid; i < NN*3; i += BLOCKE) sX[i] = x[i];
    __syncthreads();

    const float xr0 = sX[rcv*3+0], xr1 = sX[rcv*3+1], xr2 = sX[rcv*3+2];

    float acc[24];
    #pragma unroll
    for (int i = 0; i < 24; i++) acc[i] = 0.f;

    for (int t0 = 0; t0 < NN; t0 += TILE) {
        __syncthreads();
        for (int i = tid; i < 64*TILE; i += BLOCKE) {
            int f = i >> 7, e = i & 127;
            sEST[i] = g_hsT[f*NN + t0 + e];
        }
        for (int i = tid; i < 48*TILE; i += BLOCKE) {
            int f = i >> 7, e = i & 127;
            sEVT[i] = g_hvT[f*NN + t0 + e];
        }
        if (tid < 512) {
            const int e  = tid & 127;
            const int g  = tid >> 7;
            const int s  = t0 + e;
            const float vx = xr0 - sX[s*3+0];
            const float vy = xr1 - sX[s*3+1];
            const float vz = xr2 - sX[s*3+2];
            const float rr = sqrtf(vx*vx + vy*vy + vz*vz);
            const bool self = (s == rcv);
            const float rinv = self ? 0.f : (1.f / rr);
            if (g == 0) {
                sRHT[0*128+e] = vx*rinv;
                sRHT[1*128+e] = vy*rinv;
                sRHT[2*128+e] = vz*rinv;
            }
            const float rg = self ? 1.f : rr;
            float sa, ca;
            __sincosf(0.31415926535f * rg, &sa, &ca);
            const float coef = 0.4472135955f * rinv;
            u64 rbp[8];
            {
                float sp = 0.f, sc = sa;
                const float twoc = 2.f*ca;
                #pragma unroll
                for (int nb = 0; nb < 8; nb++) {
                    float rb = sc * coef;
                    rbp[nb] = pack2(rb, rb);
                    float sn = fmaf(twoc, sc, -sp);
                    sp = sc; sc = sn;
                }
            }
            const float u = 2.f * (1.f - rr*0.1f);
            const float env = (!self && u > 0.f) ? 1.2f*__expf(-1.f/u) : 0.f;
            const u64* W1p = (const u64*)sW1;
            const u64* B1p = (const u64*)sB1;
            #pragma unroll
            for (int k = 0; k < 8; k++) {
                const int h = g*16 + 2*k;
                u64 t2 = B1p[h >> 1];
                #pragma unroll
                for (int nb = 0; nb < 8; nb++)
                    t2 = fma2(rbp[nb], W1p[(nb*64 + h) >> 1], t2);
                float ta, tb; unpack2(t2, ta, tb);
                const float h0 = env * __fdividef(ta, 1.f + __expf(-ta));
                const float h1 = env * __fdividef(tb, 1.f + __expf(-tb));
                *(float2*)(sH2 + (h >> 1)*256 + e*2) = make_float2(h0, h1);
            }
        }
        __syncthreads();
        {
            u64 racc[16];
            #pragma unroll
            for (int i = 0; i < 16; i++) racc[i] = 0ull;
            #pragma unroll 4
            for (int kk = 0; kk < 32; kk++) {
                const float2* hp = (const float2*)(sH2 + kk*256) + lane;
                float2 f0 = hp[0], f1 = hp[32], f2v = hp[64], f3v = hp[96];
                const u64* w0 = (const u64*)(sW2 + (2*kk)*176 + pbase);
                const u64* w1r = (const u64*)(sW2 + (2*kk+1)*176 + pbase);
                ulonglong2 wA0 = *(const ulonglong2*)w0;
                ulonglong2 wB0 = *(const ulonglong2*)(w0 + 2);
                ulonglong2 wA1 = *(const ulonglong2*)w1r;
                ulonglong2 wB1 = *(const ulonglong2*)(w1r + 2);
                u64 d00 = pack2(f0.x, f0.x), d01 = pack2(f0.y, f0.y);
                u64 d10 = pack2(f1.x, f1.x), d11 = pack2(f1.y, f1.y);
                u64 d20 = pack2(f2v.x, f2v.x), d21 = pack2(f2v.y, f2v.y);
                u64 d30 = pack2(f3v.x, f3v.x), d31 = pack2(f3v.y, f3v.y);
                racc[0]  = fma2(d00, wA0.x, racc[0]);
                racc[1]  = fma2(d10, wA0.x, racc[1]);
                racc[2]  = fma2(d20, wA0.x, racc[2]);
                racc[3]  = fma2(d30, wA0.x, racc[3]);
                racc[4]  = fma2(d00, wA0.y, racc[4]);
                racc[5]  = fma2(d10, wA0.y, racc[5]);
                racc[6]  = fma2(d20, wA0.y, racc[6]);
                racc[7]  = fma2(d30, wA0.y, racc[7]);
                racc[8]  = fma2(d00, wB0.x, racc[8]);
                racc[9]  = fma2(d10, wB0.x, racc[9]);
                racc[10] = fma2(d20, wB0.x, racc[10]);
                racc[11] = fma2(d30, wB0.x, racc[11]);
                racc[12] = fma2(d00, wB0.y, racc[12]);
                racc[13] = fma2(d10, wB0.y, racc[13]);
                racc[14] = fma2(d20, wB0.y, racc[14]);
                racc[15] = fma2(d30, wB0.y, racc[15]);
                racc[0]  = fma2(d01, wA1.x, racc[0]);
                racc[1]  = fma2(d11, wA1.x, racc[1]);
                racc[2]  = fma2(d21, wA1.x, racc[2]);
                racc[3]  = fma2(d31, wA1.x, racc[3]);
                racc[4]  = fma2(d01, wA1.y, racc[4]);
                racc[5]  = fma2(d11, wA1.y, racc[5]);
                racc[6]  = fma2(d21, wA1.y, racc[6]);
                racc[7]  = fma2(d31, wA1.y, racc[7]);
                racc[8]  = fma2(d01, wB1.x, racc[8]);
                racc[9]  = fma2(d11, wB1.x, racc[9]);
                racc[10] = fma2(d21, wB1.x, racc[10]);
                racc[11] = fma2(d31, wB1.x, racc[11]);
                racc[12] = fma2(d01, wB1.y, racc[12]);
                racc[13] = fma2(d11, wB1.y, racc[13]);
                racc[14] = fma2(d21, wB1.y, racc[14]);
                racc[15] = fma2(d31, wB1.y, racc[15]);
            }
            #pragma unroll
            for (int m = 0; m < 4; m++) {
                const int le = lane + 32*m;
                if (cls == 0) {
                    #pragma unroll
                    for (int pj = 0; pj < 4; pj++) {
                        float R0, R1; unpack2(racc[pj*4+m], R0, R1);
                        acc[2*pj]   = fmaf(sEST[(pbase+2*pj)*128 + le],   R0, acc[2*pj]);
                        acc[2*pj+1] = fmaf(sEST[(pbase+2*pj+1)*128 + le], R1, acc[2*pj+1]);
                    }
                } else if (cls == 1) {
                    const float rx = sRHT[le], ry = sRHT[128+le], rz = sRHT[256+le];
                    #pragma unroll
                    for (int pj = 0; pj < 4; pj++) {
                        float R0, R1; unpack2(racc[pj*4+m], R0, R1);
                        const int i0 = pbase + 2*pj - 64;
                        float d0 = sEVT[(i0*3+0)*128+le]*rx + sEVT[(i0*3+1)*128+le]*ry + sEVT[(i0*3+2)*128+le]*rz;
                        float d1 = sEVT[((i0+1)*3+0)*128+le]*rx + sEVT[((i0+1)*3+1)*128+le]*ry + sEVT[((i0+1)*3+2)*128+le]*rz;
                        acc[2*pj]   = fmaf(d0, R0, acc[2*pj]);
                        acc[2*pj+1] = fmaf(d1, R1, acc[2*pj+1]);
                    }
                } else if (cls == 2) {
                    const float rx = sRHT[le], ry = sRHT[128+le], rz = sRHT[256+le];
                    #pragma unroll
                    for (int pj = 0; pj < 4; pj++) {
                        float R0, R1; unpack2(racc[pj*4+m], R0, R1);
                        const int i0 = pbase + 2*pj - 80;
                        const float t0_ = sEST[i0*128 + le] * R0;
                        const float t1_ = sEST[(i0+1)*128 + le] * R1;
                        acc[(2*pj)*3+0] = fmaf(t0_, rx, acc[(2*pj)*3+0]);
                        acc[(2*pj)*3+1] = fmaf(t0_, ry, acc[(2*pj)*3+1]);
                        acc[(2*pj)*3+2] = fmaf(t0_, rz, acc[(2*pj)*3+2]);
                        acc[(2*pj+1)*3+0] = fmaf(t1_, rx, acc[(2*pj+1)*3+0]);
                        acc[(2*pj+1)*3+1] = fmaf(t1_, ry, acc[(2*pj+1)*3+1]);
                        acc[(2*pj+1)*3+2] = fmaf(t1_, rz, acc[(2*pj+1)*3+2]);
                    }
                } else if (cls == 3) {
                    #pragma unroll
                    for (int pj = 0; pj < 4; pj++) {
                        float R0, R1; unpack2(racc[pj*4+m], R0, R1);
                        const int i0 = pbase + 2*pj - 144;
                        #pragma unroll
                        for (int c = 0; c < 3; c++) {
                            acc[(2*pj)*3+c]   = fmaf(sEVT[(i0*3+c)*128+le],     R0, acc[(2*pj)*3+c]);
                            acc[(2*pj+1)*3+c] = fmaf(sEVT[((i0+1)*3+c)*128+le], R1, acc[(2*pj+1)*3+c]);
                        }
                    }
                } else {
                    const float rx = sRHT[le], ry = sRHT[128+le], rz = sRHT[256+le];
                    #pragma unroll
                    for (int pj = 0; pj < 4; pj++) {
                        float R0, R1; unpack2(racc[pj*4+m], R0, R1);
                        const int i0 = pbase + 2*pj - 160;
                        float e0x = sEVT[(i0*3+0)*128+le], e0y = sEVT[(i0*3+1)*128+le], e0z = sEVT[(i0*3+2)*128+le];
                        float e1x = sEVT[((i0+1)*3+0)*128+le], e1y = sEVT[((i0+1)*3+1)*128+le], e1z = sEVT[((i0+1)*3+2)*128+le];
                        acc[(2*pj)*3+0] = fmaf(e0y*rz - e0z*ry, R0, acc[(2*pj)*3+0]);
                        acc[(2*pj)*3+1] = fmaf(e0z*rx - e0x*rz, R0, acc[(2*pj)*3+1]);
                        acc[(2*pj)*3+2] = fmaf(e0x*ry - e0y*rx, R0, acc[(2*pj)*3+2]);
                        acc[(2*pj+1)*3+0] = fmaf(e1y*rz - e1z*ry, R1, acc[(2*pj+1)*3+0]);
                        acc[(2*pj+1)*3+1] = fmaf(e1z*rx - e1x*rz, R1, acc[(2*pj+1)*3+1]);
                        acc[(2*pj+1)*3+2] = fmaf(e1x*ry - e1y*rx, R1, acc[(2*pj+1)*3+2]);
                    }
                }
            }
        }
    }
    #pragma unroll
    for (int i = 0; i < 24; i++) {
        #pragma unroll
        for (int o = 16; o > 0; o >>= 1)
            acc[i] += __shfl_xor_sync(0xffffffffu, acc[i], o);
    }
    if (lane == 0) {
        if (cls <= 1) {
            #pragma unroll
            for (int j = 0; j < 8; j++)
                g_aggs[rcv*80 + pbase + j] = acc[j] * AVGI;
        } else {
            const int rbase = (cls == 2) ? (pbase - 80) : (cls == 3 ? 64 + (pbase - 144) : 80 + (pbase - 160));
            #pragma unroll
            for (int j = 0; j < 8; j++) {
                const int base = rcv*288 + (rbase + j)*3;
                g_aggv[base+0] = acc[j*3+0] * AVGI;
                g_aggv[base+1] = acc[j*3+1] * AVGI;
                g_aggv[base+2] = acc[j*3+2] * AVGI;
            }
        }
    }
}

// ---------------- node update (+ fused next-layer transform) ----------------
__global__ void node_update(const float* __restrict__ wmix_s,
                            const float* __restrict__ wmix_v,
                            const float* __restrict__ wgate,
                            const float* __restrict__ wro_s,
                            const float* __restrict__ wro_v,
                            const float* __restrict__ wns_next,
                            const float* __restrict__ wnv_next,
                            float* __restrict__ out_s,
                            float* __restrict__ out_v,
                            int first, int last) {
    int n = blockIdx.x, t = threadIdx.x;   // 128 threads
    __shared__ float sA[80], sV[288], sM[64], sS[64], sG[16], sMV[48];
    if (t < 80) sA[t] = g_aggs[n*80 + t];
    for (int i = t; i < 288; i += 128) sV[i] = g_aggv[n*288 + i];
    __syncthreads();
    if (t < 64) {
        float m = 0.f;
        #pragma unroll
        for (int p = 0; p < 80; p++) m = fmaf(sA[p], wmix_s[p*64 + t], m);
        sM[t] = m;
        sS[t] = m / (1.f + __expf(-m));
    }
    if (t >= 64 && t < 112) {
        int i = t - 64, v = i/3, c = i - v*3;
        float m = 0.f;
        #pragma unroll
        for (int p = 0; p < 96; p++) m = fmaf(sV[p*3 + c], wmix_v[p*16 + v], m);
        sMV[i] = m;
    }
    __syncthreads();
    if (t < 16) {
        float g = 0.f;
        #pragma unroll
        for (int f = 0; f < 64; f++) g = fmaf(sM[f], wgate[f*16 + t], g);
        sG[t] = 1.f / (1.f + __expf(-g));
    }
    __syncthreads();
    if (t < 48) {
        int v = t/3;
        sMV[t] = sG[v] * sMV[t];
    }
    __syncthreads();
    if (t < 32) {
        float o = 0.f;
        #pragma unroll
        for (int f = 0; f < 64; f++) o = fmaf(sS[f], wro_s[f*32 + t], o);
        if (first) out_s[n*32 + t] = o; else out_s[n*32 + t] += o;
    }
    if (t >= 64 && t < 112) {
        int i = t - 64, k = i/3, c = i - k*3;
        float o = 0.f;
        #pragma unroll
        for (int v = 0; v < 16; v++) o = fmaf(sMV[v*3 + c], wro_v[v*16 + k], o);
        float prev = first ? 0.f : out_v[n*48 + i];
        o += prev;
        if (last) o += g_com[c];
        out_v[n*48 + i] = o;
    }
    if (!last) {
        if (t < 64) {
            float a = 0.f;
            #pragma unroll
            for (int k = 0; k < 64; k++) a = fmaf(sS[k], wns_next[k*64 + t], a);
            g_hsT[t*NN + n] = a;
        }
        if (t >= 64 && t < 112) {
            int i = t - 64, wv = i/3, c = i - wv*3;
            float a = 0.f;
            #pragma unroll
            for (int v = 0; v < 16; v++) a = fmaf(sMV[v*3 + c], wnv_next[v*16 + wv], a);
            g_hvT[i*NN + n] = a;
        }
    }
}

// ---------------- launch ----------------
extern "C" void kernel_launch(void* const* d_in, const int* in_sizes, int n_in,
                              void* d_out, int out_size) {
    const float* x      = (const float*)d_in[0];
    const float* embed  = (const float*)d_in[1];
    const float* wns    = (const float*)d_in[2];
    const float* wnv    = (const float*)d_in[3];
    const float* wr1    = (const float*)d_in[4];
    const float* br1    = (const float*)d_in[5];
    const float* wr2    = (const float*)d_in[6];
    const float* wmixs  = (const float*)d_in[7];
    const float* wmixv  = (const float*)d_in[8];
    const float* wgate  = (const float*)d_in[9];
    const float* wros   = (const float*)d_in[10];
    const float* wrov   = (const float*)d_in[11];

    float* out   = (float*)d_out;
    float* out_s = out;
    float* out_v = out + NN*ROS;

    cudaFuncSetAttribute(edge_kernel,
        cudaFuncAttributeMaxDynamicSharedMemorySize, SMEM_BYTES);
    cudaFuncSetAttribute(edge0_kernel,
        cudaFuncAttributeMaxDynamicSharedMemorySize, SMEM0_BYTES);

    prep0<<<1, NN>>>(x, embed, wns);

    // layer 0: collapsed edge kernel
    edge0_kernel<<<NN, 512, SMEM0_BYTES>>>(x, wr1, br1, wr2);
    node_update<<<NN, 128>>>(
        wmixs, wmixv, wgate, wros, wrov,
        wns + FF*FF, wnv + VV*VV,
        out_s, out_v, 1, 0);

    // layer 1: full edge kernel
    edge_kernel<<<NN, BLOCKE, SMEM_BYTES>>>(
        x, wr1 + NB*HR, br1 + HR, wr2 + HR*PP);
    node_update<<<NN, 128>>>(
        wmixs + 80*64, wmixv + 96*16, wgate + 64*16,
        wros + 64*32, wrov + 16*16,
        wns, wnv,
        out_s, out_v, 0, 1);
}

// round 12
// speedup vs baseline: 1.5936x; 1.0204x over previous
#include <cuda_runtime.h>
#include <cuda_bf16.h>
#include <math.h>
#include <stdint.h>

// ---------------- problem constants ----------------
#define NN   768
#define FF   64
#define VV   16
#define NB   8
#define HR   64
#define TT   2
#define ROS  32
#define ROV  16
#define PP   176
#define AVGI (1.0f/767.0f)

#define TILE   128
#define BLOCKE 704        // layer-1 edge kernel: 22 warps

// layer-1 shared memory float offsets
#define OFF_H2    0            // [32][128][2]
#define OFF_EST   8192         // [64][128]
#define OFF_EVT   16384        // [48][128]
#define OFF_RHT   22528        // [3][128] + pad
#define OFF_W2    22912        // [64][176]
#define OFF_W1    34176        // [8][64]
#define OFF_B1    34688        // [64]
#define OFF_X     34752        // [768*3]
#define SMEM_FLOATS 37056
#define SMEM_BYTES  (SMEM_FLOATS*4)

// layer-0 shared memory float offsets
#define Z_H2    0
#define Z_RHT   8192
#define Z_W1    8704
#define Z_B1    9216
#define Z_ES0   9280
#define Z_SUM   9344
#define Z_X     9600
#define Z_W2    11904
#define SMEM0_FLOATS 23168
#define SMEM0_BYTES  (SMEM0_FLOATS*4)

typedef unsigned long long u64;

__device__ __forceinline__ u64 pack2(float lo, float hi) {
    u64 r; asm("mov.b64 %0,{%1,%2};" : "=l"(r) : "f"(lo), "f"(hi)); return r;
}
__device__ __forceinline__ void unpack2(u64 v, float& lo, float& hi) {
    asm("mov.b64 {%0,%1},%2;" : "=f"(lo), "=f"(hi) : "l"(v));
}
__device__ __forceinline__ u64 fma2(u64 a, u64 b, u64 c) {
    u64 d; asm("fma.rn.f32x2 %0,%1,%2,%3;" : "=l"(d) : "l"(a), "l"(b), "l"(c)); return d;
}

// ---------------- device scratch ----------------
__device__ float g_hsT[FF*NN];
__device__ float g_hvT[48*NN];
__device__ float g_hs0[FF];
__device__ float g_aggsH[2][NN*80];
__device__ float g_aggvH[2][NN*288];
__device__ float g_com[3];

// ---------------- prep0 ----------------
__global__ void prep0(const float* __restrict__ x,
                      const float* __restrict__ embed,
                      const float* __restrict__ wns0) {
    __shared__ float s0[24], s1[24], s2[24];
    int i = threadIdx.x;           // 768 threads
    float v0 = x[i*3+0], v1 = x[i*3+1], v2 = x[i*3+2];
    #pragma unroll
    for (int o = 16; o > 0; o >>= 1) {
        v0 += __shfl_down_sync(0xffffffffu, v0, o);
        v1 += __shfl_down_sync(0xffffffffu, v1, o);
        v2 += __shfl_down_sync(0xffffffffu, v2, o);
    }
    if ((i & 31) == 0) { s0[i>>5]=v0; s1[i>>5]=v1; s2[i>>5]=v2; }
    if (i < 64) {
        float a = 0.f;
        #pragma unroll
        for (int k = 0; k < 64; k++) a = fmaf(embed[k], wns0[k*64 + i], a);
        g_hs0[i] = a;
    }
    __syncthreads();
    if (i == 0) {
        float a0=0,a1=0,a2=0;
        for (int w = 0; w < 24; w++) { a0+=s0[w]; a1+=s1[w]; a2+=s2[w]; }
        g_com[0]=a0/768.f; g_com[1]=a1/768.f; g_com[2]=a2/768.f;
    }
    for (int j = i; j < 48*NN; j += 768) g_hvT[j] = 0.f;
}

// ---------------- layer-0 edge kernel: collapsed sums ----------------
__global__ __launch_bounds__(512, 2)
void edge0_kernel(const float* __restrict__ x,
                  const float* __restrict__ w1, const float* __restrict__ b1,
                  const float* __restrict__ w2) {
    extern __shared__ float sm[];
    float* sH2  = sm + Z_H2;
    float* sRHT = sm + Z_RHT;
    float* sW1  = sm + Z_W1;
    float* sB1  = sm + Z_B1;
    float* sES0 = sm + Z_ES0;
    float* sSUM = sm + Z_SUM;
    float* sX   = sm + Z_X;
    float* sW2  = sm + Z_W2;

    const int tid  = threadIdx.x;
    const int lane = tid & 31;
    const int w    = tid >> 5;
    const int rcv  = blockIdx.x;

    for (int i = tid; i < 512; i += 512) sW1[i] = w1[i];
    if (tid < 64) { sB1[tid] = b1[tid]; sES0[tid] = g_hs0[tid]; }
    for (int i = tid; i < PP*64; i += 512) sW2[i] = w2[i];
    for (int i = tid; i < NN*3; i += 512) sX[i] = x[i];
    __syncthreads();

    const float xr0 = sX[rcv*3+0], xr1 = sX[rcv*3+1], xr2 = sX[rcv*3+2];

    const int styp = w & 3;
    const int kpb  = (w >> 2) * 8;
    u64 acc[8];
    #pragma unroll
    for (int i = 0; i < 8; i++) acc[i] = 0ull;

    for (int t0 = 0; t0 < NN; t0 += TILE) {
        __syncthreads();
        {
            const int e  = tid & 127;
            const int g  = tid >> 7;
            const int s  = t0 + e;
            const float vx = xr0 - sX[s*3+0];
            const float vy = xr1 - sX[s*3+1];
            const float vz = xr2 - sX[s*3+2];
            const float rr = sqrtf(vx*vx + vy*vy + vz*vz);
            const bool self = (s == rcv);
            const float rinv = self ? 0.f : (1.f / rr);
            if (g == 0) {
                sRHT[0*128+e] = vx*rinv;
                sRHT[1*128+e] = vy*rinv;
                sRHT[2*128+e] = vz*rinv;
            }
            const float rg = self ? 1.f : rr;
            float sa, ca;
            __sincosf(0.31415926535f * rg, &sa, &ca);
            const float coef = 0.4472135955f * rinv;
            u64 rbp[8];
            {
                float sp = 0.f, sc = sa;
                const float twoc = 2.f*ca;
                #pragma unroll
                for (int nb = 0; nb < 8; nb++) {
                    float rb = sc * coef;
                    rbp[nb] = pack2(rb, rb);
                    float sn = fmaf(twoc, sc, -sp);
                    sp = sc; sc = sn;
                }
            }
            const float u = 2.f * (1.f - rr*0.1f);
            const float env = (!self && u > 0.f) ? 1.2f*__expf(-1.f/u) : 0.f;
            const u64* W1p = (const u64*)sW1;
            const u64* B1p = (const u64*)sB1;
            #pragma unroll
            for (int k = 0; k < 8; k++) {
                const int h = g*16 + 2*k;
                u64 t2 = B1p[h >> 1];
                #pragma unroll
                for (int nb = 0; nb < 8; nb++)
                    t2 = fma2(rbp[nb], W1p[(nb*64 + h) >> 1], t2);
                float ta, tb; unpack2(t2, ta, tb);
                const float h0 = env * __fdividef(ta, 1.f + __expf(-ta));
                const float h1 = env * __fdividef(tb, 1.f + __expf(-tb));
                *(float2*)(sH2 + (h >> 1)*256 + e*2) = make_float2(h0, h1);
            }
        }
        __syncthreads();
        #pragma unroll
        for (int m = 0; m < 4; m++) {
            const int le = lane + 32*m;
            const float wt = (styp == 0) ? 1.f : sRHT[(styp-1)*128 + le];
            const u64 wd = pack2(wt, wt);
            #pragma unroll
            for (int kp = 0; kp < 8; kp++) {
                u64 hv = *(const u64*)(sH2 + (kpb + kp)*256 + le*2);
                acc[kp] = fma2(hv, wd, acc[kp]);
            }
        }
    }
    {
        float a0[8], a1[8];
        #pragma unroll
        for (int kp = 0; kp < 8; kp++) unpack2(acc[kp], a0[kp], a1[kp]);
        #pragma unroll
        for (int kp = 0; kp < 8; kp++) {
            #pragma unroll
            for (int o = 16; o > 0; o >>= 1) {
                a0[kp] += __shfl_xor_sync(0xffffffffu, a0[kp], o);
                a1[kp] += __shfl_xor_sync(0xffffffffu, a1[kp], o);
            }
        }
        if (lane == 0) {
            #pragma unroll
            for (int kp = 0; kp < 8; kp++) {
                sSUM[styp*64 + (kpb+kp)*2 + 0] = a0[kp];
                sSUM[styp*64 + (kpb+kp)*2 + 1] = a1[kp];
            }
        }
    }
    __syncthreads();
    if (tid < 256) {
        const int t = tid >> 6;
        const int pr = tid & 63;
        const int p = (t == 0) ? pr : (80 + pr);
        const float* S = sSUM + t*64;
        float dot = 0.f;
        #pragma unroll
        for (int k = 0; k < 64; k++) dot = fmaf(S[k], sW2[k*176 + p], dot);
        const float v = sES0[pr] * dot * AVGI;
        if (t == 0) g_aggsH[0][rcv*80 + pr] = v;
        else        g_aggvH[0][rcv*288 + pr*3 + (t-1)] = v;
    } else if (tid < 272) {
        g_aggsH[0][rcv*80 + 64 + (tid - 256)] = 0.f;
    } else if (tid < 368) {
        g_aggvH[0][rcv*288 + 192 + (tid - 272)] = 0.f;
    }
}

// ---------------- layer-1 edge kernel: grid=1536, EST prefetch ----------------
__global__ __launch_bounds__(BLOCKE, 1)
void edge_kernel(const float* __restrict__ x,
                 const float* __restrict__ w1, const float* __restrict__ b1,
                 const float* __restrict__ w2) {
    extern __shared__ float sm[];
    float* sH2  = sm + OFF_H2;
    float* sEST = sm + OFF_EST;
    float* sEVT = sm + OFF_EVT;
    float* sRHT = sm + OFF_RHT;
    float* sW2  = sm + OFF_W2;
    float* sW1  = sm + OFF_W1;
    float* sB1  = sm + OFF_B1;
    float* sX   = sm + OFF_X;

    const int tid  = threadIdx.x;
    const int lane = tid & 31;
    const int w    = tid >> 5;
    const int rcv  = blockIdx.x >> 1;
    const int bh   = blockIdx.x & 1;
    const int pbase = w * 8;

    int cls;
    if      (w < 8)  cls = 0;
    else if (w < 10) cls = 1;
    else if (w < 18) cls = 2;
    else if (w < 20) cls = 3;
    else             cls = 4;

    for (int i = tid; i < 512; i += BLOCKE) sW1[i] = w1[i];
    if (tid < 64) sB1[tid] = b1[tid];
    for (int i = tid; i < PP*64; i += BLOCKE) sW2[i] = w2[i];
    for (int i = tid; i < NN*3; i += BLOCKE) sX[i] = x[i];
    __syncthreads();

    const float xr0 = sX[rcv*3+0], xr1 = sX[rcv*3+1], xr2 = sX[rcv*3+2];

    float acc[24];
    #pragma unroll
    for (int i = 0; i < 24; i++) acc[i] = 0.f;

    const int tbeg = bh * 384;

    // prefetch EST for first tile: idx over 2048 float4 (f = idx>>5, e4 = idx&31)
    float4 pf[3];
    #pragma unroll
    for (int j = 0; j < 3; j++) {
        int idx = tid + j*BLOCKE;
        if (idx < 2048)
            pf[j] = *(const float4*)(g_hsT + (idx >> 5)*NN + tbeg + (idx & 31)*4);
    }

    for (int tt = 0; tt < 3; tt++) {
        const int t0 = tbeg + tt*TILE;
        __syncthreads();
        // write prefetched EST
        #pragma unroll
        for (int j = 0; j < 3; j++) {
            int idx = tid + j*BLOCKE;
            if (idx < 2048) ((float4*)sEST)[idx] = pf[j];
        }
        // stage EVT (float4)
        #pragma unroll
        for (int j = 0; j < 3; j++) {
            int idx = tid + j*BLOCKE;
            if (idx < 1536)
                ((float4*)sEVT)[idx] = *(const float4*)(g_hvT + (idx >> 5)*NN + t0 + (idx & 31)*4);
        }
        // phase 1
        if (tid < 512) {
            const int e  = tid & 127;
            const int g  = tid >> 7;
            const int s  = t0 + e;
            const float vx = xr0 - sX[s*3+0];
            const float vy = xr1 - sX[s*3+1];
            const float vz = xr2 - sX[s*3+2];
            const float rr = sqrtf(vx*vx + vy*vy + vz*vz);
            const bool self = (s == rcv);
            const float rinv = self ? 0.f : (1.f / rr);
            if (g == 0) {
                sRHT[0*128+e] = vx*rinv;
                sRHT[1*128+e] = vy*rinv;
                sRHT[2*128+e] = vz*rinv;
            }
            const float rg = self ? 1.f : rr;
            float sa, ca;
            __sincosf(0.31415926535f * rg, &sa, &ca);
            const float coef = 0.4472135955f * rinv;
            u64 rbp[8];
            {
                float sp = 0.f, sc = sa;
                const float twoc = 2.f*ca;
                #pragma unroll
                for (int nb = 0; nb < 8; nb++) {
                    float rb = sc * coef;
                    rbp[nb] = pack2(rb, rb);
                    float sn = fmaf(twoc, sc, -sp);
                    sp = sc; sc = sn;
                }
            }
            const float u = 2.f * (1.f - rr*0.1f);
            const float env = (!self && u > 0.f) ? 1.2f*__expf(-1.f/u) : 0.f;
            const u64* W1p = (const u64*)sW1;
            const u64* B1p = (const u64*)sB1;
            #pragma unroll
            for (int k = 0; k < 8; k++) {
                const int h = g*16 + 2*k;
                u64 t2 = B1p[h >> 1];
                #pragma unroll
                for (int nb = 0; nb < 8; nb++)
                    t2 = fma2(rbp[nb], W1p[(nb*64 + h) >> 1], t2);
                float ta, tb; unpack2(t2, ta, tb);
                const float h0 = env * __fdividef(ta, 1.f + __expf(-ta));
                const float h1 = env * __fdividef(tb, 1.f + __expf(-tb));
                *(float2*)(sH2 + (h >> 1)*256 + e*2) = make_float2(h0, h1);
            }
        }
        // prefetch next tile's EST; LDG latency overlaps phase 2
        if (tt < 2) {
            #pragma unroll
            for (int j = 0; j < 3; j++) {
                int idx = tid + j*BLOCKE;
                if (idx < 2048)
                    pf[j] = *(const float4*)(g_hsT + (idx >> 5)*NN + (t0 + TILE) + (idx & 31)*4);
            }
        }
        __syncthreads();
        // phase 2
        {
            u64 racc[16];
            #pragma unroll
            for (int i = 0; i < 16; i++) racc[i] = 0ull;
            #pragma unroll 4
            for (int kk = 0; kk < 32; kk++) {
                const float2* hp = (const float2*)(sH2 + kk*256) + lane;
                float2 f0 = hp[0], f1 = hp[32], f2v = hp[64], f3v = hp[96];
                const u64* w0 = (const u64*)(sW2 + (2*kk)*176 + pbase);
                const u64* w1r = (const u64*)(sW2 + (2*kk+1)*176 + pbase);
                ulonglong2 wA0 = *(const ulonglong2*)w0;
                ulonglong2 wB0 = *(const ulonglong2*)(w0 + 2);
                ulonglong2 wA1 = *(const ulonglong2*)w1r;
                ulonglong2 wB1 = *(const ulonglong2*)(w1r + 2);
                u64 d00 = pack2(f0.x, f0.x), d01 = pack2(f0.y, f0.y);
                u64 d10 = pack2(f1.x, f1.x), d11 = pack2(f1.y, f1.y);
                u64 d20 = pack2(f2v.x, f2v.x), d21 = pack2(f2v.y, f2v.y);
                u64 d30 = pack2(f3v.x, f3v.x), d31 = pack2(f3v.y, f3v.y);
                racc[0]  = fma2(d00, wA0.x, racc[0]);
                racc[1]  = fma2(d10, wA0.x, racc[1]);
                racc[2]  = fma2(d20, wA0.x, racc[2]);
                racc[3]  = fma2(d30, wA0.x, racc[3]);
                racc[4]  = fma2(d00, wA0.y, racc[4]);
                racc[5]  = fma2(d10, wA0.y, racc[5]);
                racc[6]  = fma2(d20, wA0.y, racc[6]);
                racc[7]  = fma2(d30, wA0.y, racc[7]);
                racc[8]  = fma2(d00, wB0.x, racc[8]);
                racc[9]  = fma2(d10, wB0.x, racc[9]);
                racc[10] = fma2(d20, wB0.x, racc[10]);
                racc[11] = fma2(d30, wB0.x, racc[11]);
                racc[12] = fma2(d00, wB0.y, racc[12]);
                racc[13] = fma2(d10, wB0.y, racc[13]);
                racc[14] = fma2(d20, wB0.y, racc[14]);
                racc[15] = fma2(d30, wB0.y, racc[15]);
                racc[0]  = fma2(d01, wA1.x, racc[0]);
                racc[1]  = fma2(d11, wA1.x, racc[1]);
                racc[2]  = fma2(d21, wA1.x, racc[2]);
                racc[3]  = fma2(d31, wA1.x, racc[3]);
                racc[4]  = fma2(d01, wA1.y, racc[4]);
                racc[5]  = fma2(d11, wA1.y, racc[5]);
                racc[6]  = fma2(d21, wA1.y, racc[6]);
                racc[7]  = fma2(d31, wA1.y, racc[7]);
                racc[8]  = fma2(d01, wB1.x, racc[8]);
                racc[9]  = fma2(d11, wB1.x, racc[9]);
                racc[10] = fma2(d21, wB1.x, racc[10]);
                racc[11] = fma2(d31, wB1.x, racc[11]);
                racc[12] = fma2(d01, wB1.y, racc[12]);
                racc[13] = fma2(d11, wB1.y, racc[13]);
                racc[14] = fma2(d21, wB1.y, racc[14]);
                racc[15] = fma2(d31, wB1.y, racc[15]);
            }
            #pragma unroll
            for (int m = 0; m < 4; m++) {
                const int le = lane + 32*m;
                if (cls == 0) {
                    #pragma unroll
                    for (int pj = 0; pj < 4; pj++) {
                        float R0, R1; unpack2(racc[pj*4+m], R0, R1);
                        acc[2*pj]   = fmaf(sEST[(pbase+2*pj)*128 + le],   R0, acc[2*pj]);
                        acc[2*pj+1] = fmaf(sEST[(pbase+2*pj+1)*128 + le], R1, acc[2*pj+1]);
                    }
                } else if (cls == 1) {
                    const float rx = sRHT[le], ry = sRHT[128+le], rz = sRHT[256+le];
                    #pragma unroll
                    for (int pj = 0; pj < 4; pj++) {
                        float R0, R1; unpack2(racc[pj*4+m], R0, R1);
                        const int i0 = pbase + 2*pj - 64;
                        float d0 = sEVT[(i0*3+0)*128+le]*rx + sEVT[(i0*3+1)*128+le]*ry + sEVT[(i0*3+2)*128+le]*rz;
                        float d1 = sEVT[((i0+1)*3+0)*128+le]*rx + sEVT[((i0+1)*3+1)*128+le]*ry + sEVT[((i0+1)*3+2)*128+le]*rz;
                        acc[2*pj]   = fmaf(d0, R0, acc[2*pj]);
                        acc[2*pj+1] = fmaf(d1, R1, acc[2*pj+1]);
                    }
                } else if (cls == 2) {
                    const float rx = sRHT[le], ry = sRHT[128+le], rz = sRHT[256+le];
                    #pragma unroll
                    for (int pj = 0; pj < 4; pj++) {
                        float R0, R1; unpack2(racc[pj*4+m], R0, R1);
                        const int i0 = pbase + 2*pj - 80;
                        const float t0_ = sEST[i0*128 + le] * R0;
                        const float t1_ = sEST[(i0+1)*128 + le] * R1;
                        acc[(2*pj)*3+0] = fmaf(t0_, rx, acc[(2*pj)*3+0]);
                        acc[(2*pj)*3+1] = fmaf(t0_, ry, acc[(2*pj)*3+1]);
                        acc[(2*pj)*3+2] = fmaf(t0_, rz, acc[(2*pj)*3+2]);
                        acc[(2*pj+1)*3+0] = fmaf(t1_, rx, acc[(2*pj+1)*3+0]);
                        acc[(2*pj+1)*3+1] = fmaf(t1_, ry, acc[(2*pj+1)*3+1]);
                        acc[(2*pj+1)*3+2] = fmaf(t1_, rz, acc[(2*pj+1)*3+2]);
                    }
                } else if (cls == 3) {
                    #pragma unroll
                    for (int pj = 0; pj < 4; pj++) {
                        float R0, R1; unpack2(racc[pj*4+m], R0, R1);
                        const int i0 = pbase + 2*pj - 144;
                        #pragma unroll
                        for (int c = 0; c < 3; c++) {
                            acc[(2*pj)*3+c]   = fmaf(sEVT[(i0*3+c)*128+le],     R0, acc[(2*pj)*3+c]);
                            acc[(2*pj+1)*3+c] = fmaf(sEVT[((i0+1)*3+c)*128+le], R1, acc[(2*pj+1)*3+c]);
                        }
                    }
                } else {
                    const float rx = sRHT[le], ry = sRHT[128+le], rz = sRHT[256+le];
                    #pragma unroll
                    for (int pj = 0; pj < 4; pj++) {
                        float R0, R1; unpack2(racc[pj*4+m], R0, R1);
                        const int i0 = pbase + 2*pj - 160;
                        float e0x = sEVT[(i0*3+0)*128+le], e0y = sEVT[(i0*3+1)*128+le], e0z = sEVT[(i0*3+2)*128+le];
                        float e1x = sEVT[((i0+1)*3+0)*128+le], e1y = sEVT[((i0+1)*3+1)*128+le], e1z = sEVT[((i0+1)*3+2)*128+le];
                        acc[(2*pj)*3+0] = fmaf(e0y*rz - e0z*ry, R0, acc[(2*pj)*3+0]);
                        acc[(2*pj)*3+1] = fmaf(e0z*rx - e0x*rz, R0, acc[(2*pj)*3+1]);
                        acc[(2*pj)*3+2] = fmaf(e0x*ry - e0y*rx, R0, acc[(2*pj)*3+2]);
                        acc[(2*pj+1)*3+0] = fmaf(e1y*rz - e1z*ry, R1, acc[(2*pj+1)*3+0]);
                        acc[(2*pj+1)*3+1] = fmaf(e1z*rx - e1x*rz, R1, acc[(2*pj+1)*3+1]);
                        acc[(2*pj+1)*3+2] = fmaf(e1x*ry - e1y*rx, R1, acc[(2*pj+1)*3+2]);
                    }
                }
            }
        }
    }
    #pragma unroll
    for (int i = 0; i < 24; i++) {
        #pragma unroll
        for (int o = 16; o > 0; o >>= 1)
            acc[i] += __shfl_xor_sync(0xffffffffu, acc[i], o);
    }
    if (lane == 0) {
        if (cls <= 1) {
            #pragma unroll
            for (int j = 0; j < 8; j++)
                g_aggsH[bh][rcv*80 + pbase + j] = acc[j] * AVGI;
        } else {
            const int rbase = (cls == 2) ? (pbase - 80) : (cls == 3 ? 64 + (pbase - 144) : 80 + (pbase - 160));
            #pragma unroll
            for (int j = 0; j < 8; j++) {
                const int base = rcv*288 + (rbase + j)*3;
                g_aggvH[bh][base+0] = acc[j*3+0] * AVGI;
                g_aggvH[bh][base+1] = acc[j*3+1] * AVGI;
                g_aggvH[bh][base+2] = acc[j*3+2] * AVGI;
            }
        }
    }
}

// ---------------- node update ----------------
__global__ void node_update(const float* __restrict__ wmix_s,
                            const float* __restrict__ wmix_v,
                            const float* __restrict__ wgate,
                            const float* __restrict__ wro_s,
                            const float* __restrict__ wro_v,
                            const float* __restrict__ wns_next,
                            const float* __restrict__ wnv_next,
                            float* __restrict__ out_s,
                            float* __restrict__ out_v,
                            int first, int last, int halves) {
    int n = blockIdx.x, t = threadIdx.x;   // 128 threads
    __shared__ float sA[80], sV[288], sM[64], sS[64], sG[16], sMV[48];
    if (t < 80) {
        float v = g_aggsH[0][n*80 + t];
        if (halves > 1) v += g_aggsH[1][n*80 + t];
        sA[t] = v;
    }
    for (int i = t; i < 288; i += 128) {
        float v = g_aggvH[0][n*288 + i];
        if (halves > 1) v += g_aggvH[1][n*288 + i];
        sV[i] = v;
    }
    __syncthreads();
    if (t < 64) {
        float m = 0.f;
        #pragma unroll
        for (int p = 0; p < 80; p++) m = fmaf(sA[p], wmix_s[p*64 + t], m);
        sM[t] = m;
        sS[t] = m / (1.f + __expf(-m));
    }
    if (t >= 64 && t < 112) {
        int i = t - 64, v = i/3, c = i - v*3;
        float m = 0.f;
        #pragma unroll
        for (int p = 0; p < 96; p++) m = fmaf(sV[p*3 + c], wmix_v[p*16 + v], m);
        sMV[i] = m;
    }
    __syncthreads();
    if (t < 16) {
        float g = 0.f;
        #pragma unroll
        for (int f = 0; f < 64; f++) g = fmaf(sM[f], wgate[f*16 + t], g);
        sG[t] = 1.f / (1.f + __expf(-g));
    }
    __syncthreads();
    if (t < 48) {
        int v = t/3;
        sMV[t] = sG[v] * sMV[t];
    }
    __syncthreads();
    if (t < 32) {
        float o = 0.f;
        #pragma unroll
        for (int f = 0; f < 64; f++) o = fmaf(sS[f], wro_s[f*32 + t], o);
        if (first) out_s[n*32 + t] = o; else out_s[n*32 + t] += o;
    }
    if (t >= 64 && t < 112) {
        int i = t - 64, k = i/3, c = i - k*3;
        float o = 0.f;
        #pragma unroll
        for (int v = 0; v < 16; v++) o = fmaf(sMV[v*3 + c], wro_v[v*16 + k], o);
        float prev = first ? 0.f : out_v[n*48 + i];
        o += prev;
        if (last) o += g_com[c];
        out_v[n*48 + i] = o;
    }
    if (!last) {
        if (t < 64) {
            float a = 0.f;
            #pragma unroll
            for (int k = 0; k < 64; k++) a = fmaf(sS[k], wns_next[k*64 + t], a);
            g_hsT[t*NN + n] = a;
        }
        if (t >= 64 && t < 112) {
            int i = t - 64, wv = i/3, c = i - wv*3;
            float a = 0.f;
            #pragma unroll
            for (int v = 0; v < 16; v++) a = fmaf(sMV[v*3 + c], wnv_next[v*16 + wv], a);
            g_hvT[i*NN + n] = a;
        }
    }
}

// ---------------- launch ----------------
extern "C" void kernel_launch(void* const* d_in, const int* in_sizes, int n_in,
                              void* d_out, int out_size) {
    const float* x      = (const float*)d_in[0];
    const float* embed  = (const float*)d_in[1];
    const float* wns    = (const float*)d_in[2];
    const float* wnv    = (const float*)d_in[3];
    const float* wr1    = (const float*)d_in[4];
    const float* br1    = (const float*)d_in[5];
    const float* wr2    = (const float*)d_in[6];
    const float* wmixs  = (const float*)d_in[7];
    const float* wmixv  = (const float*)d_in[8];
    const float* wgate  = (const float*)d_in[9];
    const float* wros   = (const float*)d_in[10];
    const float* wrov   = (const float*)d_in[11];

    float* out   = (float*)d_out;
    float* out_s = out;
    float* out_v = out + NN*ROS;

    cudaFuncSetAttribute(edge_kernel,
        cudaFuncAttributeMaxDynamicSharedMemorySize, SMEM_BYTES);
    cudaFuncSetAttribute(edge0_kernel,
        cudaFuncAttributeMaxDynamicSharedMemorySize, SMEM0_BYTES);

    prep0<<<1, NN>>>(x, embed, wns);

    // layer 0: collapsed edge kernel
    edge0_kernel<<<NN, 512, SMEM0_BYTES>>>(x, wr1, br1, wr2);
    node_update<<<NN, 128>>>(
        wmixs, wmixv, wgate, wros, wrov,
        wns + FF*FF, wnv + VV*VV,
        out_s, out_v, 1, 0, 1);

    // layer 1: full edge kernel, split into sender-halves
    edge_kernel<<<NN*2, BLOCKE, SMEM_BYTES>>>(
        x, wr1 + NB*HR, br1 + HR, wr2 + HR*PP);
    node_update<<<NN, 128>>>(
        wmixs + 80*64, wmixv + 96*16, wgate + 64*16,
        wros + 64*32, wrov + 16*16,
        wns, wnv,
        out_s, out_v, 0, 1, 2);
}